// round 7
// baseline (speedup 1.0000x reference)
#include <cuda_runtime.h>
#include <cuda_fp16.h>
#include <cstdint>

// Problem constants
#define BW_    1024
#define NTOK   64
#define DIM_   512
#define NH_    16
#define HD_    32
#define NW_    64
#define TRIPLE 1536
#define MTOT   (BW_ * NTOK)            /* 65536 */
#define SCALE_ 0.17677669529663687f

// ---------------------------------------------------------------------------
// Scratch (allocation-free rule: __device__ globals)
// ---------------------------------------------------------------------------
__device__ __half g_qkvh[(size_t)MTOT * TRIPLE];    // fp16 qkv (~201MB)
__device__ __half g_xh[(size_t)MTOT * DIM_];
__device__ __half g_ah[(size_t)MTOT * DIM_];
__device__ __half g_w1h[TRIPLE * DIM_];
__device__ __half g_w2h[DIM_ * DIM_];
__device__ float  g_b1[TRIPLE];                      // prescaled qkv bias
__device__ float  g_cmb[(size_t)NW_ * NH_ * NTOK * NTOK];  // bias+mask (16MB)

// ---------------------------------------------------------------------------
// helpers
// ---------------------------------------------------------------------------
__device__ __forceinline__ uint32_t smem_u32(const void* p) {
    uint32_t a;
    asm("{ .reg .u64 t; cvta.to.shared.u64 t, %1; cvt.u32.u64 %0, t; }"
        : "=r"(a) : "l"(p));
    return a;
}

#define CP_ASYNC16(smem_addr, gptr) \
    asm volatile("cp.async.cg.shared.global [%0], [%1], 16;" \
                 :: "r"((uint32_t)(smem_addr)), "l"(gptr) : "memory")
#define CP_ASYNC_COMMIT() asm volatile("cp.async.commit_group;" ::: "memory")
#define CP_ASYNC_WAIT0()  asm volatile("cp.async.wait_group 0;" ::: "memory")
#define CP_ASYNC_WAIT1()  asm volatile("cp.async.wait_group 1;" ::: "memory")
#define CP_ASYNC_WAIT2()  asm volatile("cp.async.wait_group 2;" ::: "memory")

__device__ __forceinline__ void ldsm4(uint32_t* r, uint32_t addr) {
    asm volatile("ldmatrix.sync.aligned.m8n8.x4.shared.b16 {%0,%1,%2,%3}, [%4];"
                 : "=r"(r[0]), "=r"(r[1]), "=r"(r[2]), "=r"(r[3]) : "r"(addr));
}
__device__ __forceinline__ void ldsm4t(uint32_t* r, uint32_t addr) {
    asm volatile("ldmatrix.sync.aligned.m8n8.x4.trans.shared.b16 {%0,%1,%2,%3}, [%4];"
                 : "=r"(r[0]), "=r"(r[1]), "=r"(r[2]), "=r"(r[3]) : "r"(addr));
}

#define MMA_F16(d, a0, a1, a2, a3, b0, b1) \
    asm volatile("mma.sync.aligned.m16n8k16.row.col.f32.f16.f16.f32 " \
        "{%0,%1,%2,%3}, {%4,%5,%6,%7}, {%8,%9}, {%0,%1,%2,%3};" \
        : "+f"((d)[0]), "+f"((d)[1]), "+f"((d)[2]), "+f"((d)[3]) \
        : "r"(a0), "r"(a1), "r"(a2), "r"(a3), "r"(b0), "r"(b1))

// ---------------------------------------------------------------------------
// Prep kernels
// ---------------------------------------------------------------------------
__global__ __launch_bounds__(256) void convert_half(
    const float* __restrict__ in, __half* __restrict__ out, int n)
{
    int i = (blockIdx.x * 256 + threadIdx.x) * 4;
    if (i >= n) return;
    float4 v = *(const float4*)(in + i);
    __half h[4] = {__float2half(v.x), __float2half(v.y),
                   __float2half(v.z), __float2half(v.w)};
    *(uint2*)(out + i) = *(uint2*)h;
}

// qkv weight with Wq rows scaled by SCALE_
__global__ __launch_bounds__(256) void convert_w1(
    const float* __restrict__ in, __half* __restrict__ out)
{
    int i = (blockIdx.x * 256 + threadIdx.x) * 4;
    float sc = (i < 512 * 512) ? SCALE_ : 1.0f;
    float4 v = *(const float4*)(in + i);
    __half h[4] = {__float2half(v.x * sc), __float2half(v.y * sc),
                   __float2half(v.z * sc), __float2half(v.w * sc)};
    *(uint2*)(out + i) = *(uint2*)h;
}

__global__ __launch_bounds__(256) void prep_b1(
    const float* __restrict__ qkv_b, float* __restrict__ b1)
{
    int idx = blockIdx.x * 256 + threadIdx.x;
    if (idx < TRIPLE)
        b1[idx] = qkv_b[idx] * (idx < 512 ? SCALE_ : 1.0f);
}

// combined bias+mask: cmb[nw][h][i][j] = table[rel_index[ij]*16+h] + mask[nw][ij]
__global__ __launch_bounds__(256) void prep_cmb(
    const float* __restrict__ table, const int* __restrict__ rel_index,
    const float* __restrict__ mask, float* __restrict__ cmb)
{
    int t = blockIdx.x * 256 + threadIdx.x;       // over NW*NH*4096
    int ij = t & 4095;
    int h = (t >> 12) & 15;
    int nw = t >> 16;
    cmb[t] = table[rel_index[ij] * NH_ + h] + mask[(nw << 12) + ij];
}

// ---------------------------------------------------------------------------
// fp16 GEMM (NT) on mma.sync: C = A @ B^T + bias. Templated output type.
// CTA 128x128, BK=32, 256 thr (8 warps of 32x64), 4-stage cp.async ring.
// ---------------------------------------------------------------------------
#define ROWB 80
#define TILE_B (128 * ROWB)
#define STAGE_B (2 * TILE_B)
#define NSTAGE 4

template <typename OutT>
__global__ __launch_bounds__(256, 2)
void gemm_h(const __half* __restrict__ A, const __half* __restrict__ B,
            const float* __restrict__ bias, OutT* __restrict__ C,
            int Nn, int K)
{
    extern __shared__ char smem[];
    const uint32_t sbase = smem_u32(smem);

    const int tid  = threadIdx.x;
    const int lane = tid & 31;
    const int wid  = tid >> 5;
    const int wm   = (wid & 3) * 32;
    const int wn   = (wid >> 2) * 64;
    const int m0 = blockIdx.y * 128;
    const int n0 = blockIdx.x * 128;

    float acc[2][8][4];
    #pragma unroll
    for (int a = 0; a < 2; ++a)
        #pragma unroll
        for (int b = 0; b < 8; ++b)
            #pragma unroll
            for (int c = 0; c < 4; ++c) acc[a][b][c] = 0.f;

    const int nIter = K / 32;

    auto load_stage = [&](int s, int k0) {
        uint32_t st = sbase + s * STAGE_B;
        #pragma unroll
        for (int j = 0; j < 2; ++j) {
            int lin = tid + j * 256;
            int r = lin >> 2;
            int c = lin & 3;
            uint32_t dst = r * ROWB + c * 16;
            CP_ASYNC16(st + dst, A + (size_t)(m0 + r) * K + k0 + c * 8);
            CP_ASYNC16(st + TILE_B + dst, B + (size_t)(n0 + r) * K + k0 + c * 8);
        }
        CP_ASYNC_COMMIT();
    };

    load_stage(0, 0);
    load_stage(1, 32);
    load_stage(2, 64);

    const uint32_t a_row = wm + (lane & 15);
    const uint32_t a_k8  = (lane >> 4) * 8;
    const int g = lane >> 3;
    const uint32_t b_row = wn + (g >> 1) * 8 + (lane & 7);
    const uint32_t b_k8  = (g & 1) * 8;

    for (int it = 0; it < nIter; ++it) {
        int remaining = nIter - 1 - it;
        if (remaining >= 2) { CP_ASYNC_WAIT2(); }
        else if (remaining == 1) { CP_ASYNC_WAIT1(); }
        else { CP_ASYNC_WAIT0(); }
        __syncthreads();
        if (it + 3 < nIter) load_stage((it + 3) & (NSTAGE - 1), (it + 3) * 32);

        uint32_t st = sbase + (it & (NSTAGE - 1)) * STAGE_B;
        uint32_t sA = st, sB = st + TILE_B;

        #pragma unroll
        for (int ks = 0; ks < 2; ++ks) {
            uint32_t ah[2][4], bh[4][4];
            uint32_t akoff = (ks * 16 + a_k8) * 2;
            uint32_t bkoff = (ks * 16 + b_k8) * 2;
            #pragma unroll
            for (int mt = 0; mt < 2; ++mt)
                ldsm4(ah[mt], sA + (a_row + mt * 16) * ROWB + akoff);
            #pragma unroll
            for (int nt = 0; nt < 4; ++nt)
                ldsm4(bh[nt], sB + (b_row + nt * 16) * ROWB + bkoff);
            #pragma unroll
            for (int mt = 0; mt < 2; ++mt)
                #pragma unroll
                for (int nt = 0; nt < 8; ++nt) {
                    int q = nt >> 1, h = (nt & 1) * 2;
                    MMA_F16(acc[mt][nt], ah[mt][0], ah[mt][1], ah[mt][2],
                            ah[mt][3], bh[q][h], bh[q][h + 1]);
                }
        }
        // no trailing sync: next iteration's leading sync bounds warp skew;
        // the stage written at (it+3)%4 == (it-1)%4 was consumed before it.
    }

    #pragma unroll
    for (int mt = 0; mt < 2; ++mt) {
        int r0 = m0 + wm + mt * 16 + (lane >> 2);
        #pragma unroll
        for (int nt = 0; nt < 8; ++nt) {
            int col = n0 + wn + (nt >> 1) * 16 + (nt & 1) * 8 + (lane & 3) * 2;
            float b0 = __ldg(bias + col), b1 = __ldg(bias + col + 1);
            float v00 = acc[mt][nt][0] + b0, v01 = acc[mt][nt][1] + b1;
            float v10 = acc[mt][nt][2] + b0, v11 = acc[mt][nt][3] + b1;
            if (sizeof(OutT) == 2) {
                __half2 h0 = __floats2half2_rn(v00, v01);
                __half2 h1 = __floats2half2_rn(v10, v11);
                *(__half2*)((__half*)C + (size_t)r0 * Nn + col) = h0;
                *(__half2*)((__half*)C + (size_t)(r0 + 8) * Nn + col) = h1;
            } else {
                float2 f0 = {v00, v01}, f1 = {v10, v11};
                *(float2*)((float*)C + (size_t)r0 * Nn + col) = f0;
                *(float2*)((float*)C + (size_t)(r0 + 8) * Nn + col) = f1;
            }
        }
    }
}

// ---------------------------------------------------------------------------
// Attention via mma.sync: one block per (head, window), 4 warps.
// ---------------------------------------------------------------------------
#define AROWB 80   /* 32 halfs + pad */

__global__ __launch_bounds__(128) void attn_mma(
    const __half* __restrict__ qkv,      // (BW, N, 1536), Wq prescaled
    const float* __restrict__ cmb,       // (NW, NH, 64, 64) bias+mask
    __half* __restrict__ outh)           // (BW, N, DIM)
{
    const int h  = blockIdx.x;
    const int bw = blockIdx.y;
    const int tid = threadIdx.x;
    const int lane = tid & 31;
    const int wid = tid >> 5;

    __shared__ __align__(16) unsigned char sm[3 * 64 * AROWB];
    const uint32_t sbase = smem_u32(sm);
    const uint32_t sQ = sbase, sK = sbase + 64 * AROWB, sV = sbase + 2 * 64 * AROWB;

    // Load Q,K,V tiles (64x32 fp16 each) into padded smem.
    {
        const __half* src = qkv + (size_t)bw * NTOK * TRIPLE + h * HD_;
        #pragma unroll
        for (int t = 0; t < 6; ++t) {
            int lin = tid + t * 128;          // 0..767
            int m = lin >> 8;                 // 0=q 1=k 2=v
            int rem = lin & 255;
            int row = rem >> 2, c16 = rem & 3;
            uint4 val = *(const uint4*)(src + (size_t)row * TRIPLE + m * 512 + c16 * 8);
            *(uint4*)(sm + m * 64 * AROWB + row * AROWB + c16 * 16) = val;
        }
    }
    __syncthreads();

    // ---- Phase 1: S = Q @ K^T ----
    float s[8][4];
    #pragma unroll
    for (int nt = 0; nt < 8; ++nt)
        #pragma unroll
        for (int c = 0; c < 4; ++c) s[nt][c] = 0.f;

    const uint32_t a_row = wid * 16 + (lane & 15);
    const uint32_t a_k8  = (lane >> 4) * 8;
    const int g = lane >> 3;
    const uint32_t b_row = (g >> 1) * 8 + (lane & 7);
    const uint32_t b_k8  = (g & 1) * 8;

    #pragma unroll
    for (int ks = 0; ks < 2; ++ks) {
        uint32_t aq[4], bk[4][4];
        uint32_t akoff = (ks * 16 + a_k8) * 2;
        uint32_t bkoff = (ks * 16 + b_k8) * 2;
        ldsm4(aq, sQ + a_row * AROWB + akoff);
        #pragma unroll
        for (int nt = 0; nt < 4; ++nt)
            ldsm4(bk[nt], sK + (b_row + nt * 16) * AROWB + bkoff);
        #pragma unroll
        for (int nt = 0; nt < 8; ++nt) {
            int q = nt >> 1, hh = (nt & 1) * 2;
            MMA_F16(s[nt], aq[0], aq[1], aq[2], aq[3], bk[q][hh], bk[q][hh + 1]);
        }
    }

    // ---- combined bias+mask ----
    const int r = wid * 16 + (lane >> 2);
    const int cbase = (lane & 3) * 2;
    const float* crow = cmb + (((size_t)(bw & (NW_ - 1)) * NH_ + h) << 12);
    #pragma unroll
    for (int nt = 0; nt < 8; ++nt) {
        int c = nt * 8 + cbase;
        float2 c0 = *(const float2*)(crow + r * 64 + c);
        float2 c1 = *(const float2*)(crow + (r + 8) * 64 + c);
        s[nt][0] += c0.x; s[nt][1] += c0.y;
        s[nt][2] += c1.x; s[nt][3] += c1.y;
    }

    // ---- softmax over 64 cols (4 lanes per row) ----
    {
        float mx0 = -1e30f, mx1 = -1e30f;
        #pragma unroll
        for (int nt = 0; nt < 8; ++nt) {
            mx0 = fmaxf(mx0, fmaxf(s[nt][0], s[nt][1]));
            mx1 = fmaxf(mx1, fmaxf(s[nt][2], s[nt][3]));
        }
        #pragma unroll
        for (int o = 1; o <= 2; o <<= 1) {
            mx0 = fmaxf(mx0, __shfl_xor_sync(0xffffffffu, mx0, o));
            mx1 = fmaxf(mx1, __shfl_xor_sync(0xffffffffu, mx1, o));
        }
        float sm0 = 0.f, sm1 = 0.f;
        #pragma unroll
        for (int nt = 0; nt < 8; ++nt) {
            s[nt][0] = __expf(s[nt][0] - mx0); sm0 += s[nt][0];
            s[nt][1] = __expf(s[nt][1] - mx0); sm0 += s[nt][1];
            s[nt][2] = __expf(s[nt][2] - mx1); sm1 += s[nt][2];
            s[nt][3] = __expf(s[nt][3] - mx1); sm1 += s[nt][3];
        }
        #pragma unroll
        for (int o = 1; o <= 2; o <<= 1) {
            sm0 += __shfl_xor_sync(0xffffffffu, sm0, o);
            sm1 += __shfl_xor_sync(0xffffffffu, sm1, o);
        }
        float i0 = 1.f / sm0, i1 = 1.f / sm1;
        #pragma unroll
        for (int nt = 0; nt < 8; ++nt) {
            s[nt][0] *= i0; s[nt][1] *= i0;
            s[nt][2] *= i1; s[nt][3] *= i1;
        }
    }

    // ---- Phase 2: O = P @ V ----
    float o[4][4];
    #pragma unroll
    for (int nt = 0; nt < 4; ++nt)
        #pragma unroll
        for (int c = 0; c < 4; ++c) o[nt][c] = 0.f;

    const uint32_t v_row = lane & 15;
    const uint32_t v_c16 = (lane >> 4) * 16;
    #pragma unroll
    for (int kt = 0; kt < 4; ++kt) {
        __half2 pa0 = __floats2half2_rn(s[2 * kt][0], s[2 * kt][1]);
        __half2 pa1 = __floats2half2_rn(s[2 * kt][2], s[2 * kt][3]);
        __half2 pa2 = __floats2half2_rn(s[2 * kt + 1][0], s[2 * kt + 1][1]);
        __half2 pa3 = __floats2half2_rn(s[2 * kt + 1][2], s[2 * kt + 1][3]);
        uint32_t a0 = *(uint32_t*)&pa0, a1 = *(uint32_t*)&pa1;
        uint32_t a2 = *(uint32_t*)&pa2, a3 = *(uint32_t*)&pa3;
        uint32_t vb0[4], vb1[4];
        ldsm4t(vb0, sV + (kt * 16 + v_row) * AROWB + v_c16);
        ldsm4t(vb1, sV + (kt * 16 + v_row) * AROWB + 32 + v_c16);
        MMA_F16(o[0], a0, a1, a2, a3, vb0[0], vb0[1]);
        MMA_F16(o[1], a0, a1, a2, a3, vb0[2], vb0[3]);
        MMA_F16(o[2], a0, a1, a2, a3, vb1[0], vb1[1]);
        MMA_F16(o[3], a0, a1, a2, a3, vb1[2], vb1[3]);
    }

    // ---- write O (fp16) ----
    __half* obase = outh + (size_t)bw * NTOK * DIM_ + (size_t)h * HD_;
    #pragma unroll
    for (int nt = 0; nt < 4; ++nt) {
        int c = nt * 8 + cbase;
        __half2 h0 = __floats2half2_rn(o[nt][0], o[nt][1]);
        __half2 h1 = __floats2half2_rn(o[nt][2], o[nt][3]);
        *(__half2*)(obase + (size_t)r * DIM_ + c) = h0;
        *(__half2*)(obase + (size_t)(r + 8) * DIM_ + c) = h1;
    }
}

// ---------------------------------------------------------------------------
extern "C" void kernel_launch(void* const* d_in, const int* in_sizes, int n_in,
                              void* d_out, int out_size)
{
    const float* x       = (const float*)d_in[0];
    const float* mask    = (const float*)d_in[1];
    const float* qkv_w   = (const float*)d_in[2];
    const float* qkv_b   = (const float*)d_in[3];
    const float* table   = (const float*)d_in[4];
    const float* proj_w  = (const float*)d_in[5];
    const float* proj_b  = (const float*)d_in[6];
    const int*   rel_idx = (const int*)d_in[7];
    float* out = (float*)d_out;

    __half *qkvh, *xh, *ah, *w1h, *w2h;
    float *b1, *cmb;
    cudaGetSymbolAddress((void**)&qkvh, g_qkvh);
    cudaGetSymbolAddress((void**)&xh, g_xh);
    cudaGetSymbolAddress((void**)&ah, g_ah);
    cudaGetSymbolAddress((void**)&w1h, g_w1h);
    cudaGetSymbolAddress((void**)&w2h, g_w2h);
    cudaGetSymbolAddress((void**)&b1, g_b1);
    cudaGetSymbolAddress((void**)&cmb, g_cmb);

    const int gemm_smem = NSTAGE * STAGE_B;   // 81920
    cudaFuncSetAttribute(gemm_h<__half>, cudaFuncAttributeMaxDynamicSharedMemorySize,
                         gemm_smem);
    cudaFuncSetAttribute(gemm_h<float>, cudaFuncAttributeMaxDynamicSharedMemorySize,
                         gemm_smem);

    // 1) prep
    {
        int n1 = MTOT * DIM_;
        convert_half<<<n1 / 4 / 256, 256>>>(x, xh, n1);
        convert_w1<<<TRIPLE * DIM_ / 4 / 256, 256>>>(qkv_w, w1h);
        int n3 = DIM_ * DIM_;
        convert_half<<<n3 / 4 / 256, 256>>>(proj_w, w2h, n3);
        prep_b1<<<(TRIPLE + 255) / 256, 256>>>(qkv_b, b1);
        prep_cmb<<<NW_ * NH_ * NTOK * NTOK / 256, 256>>>(table, rel_idx, mask, cmb);
    }
    // 2) QKV GEMM -> fp16 qkv
    {
        dim3 grid(TRIPLE / 128, MTOT / 128);
        gemm_h<__half><<<grid, 256, gemm_smem>>>(xh, w1h, b1, qkvh, TRIPLE, DIM_);
    }
    // 3) attention (tensor-core)
    {
        dim3 grid(NH_, BW_);
        attn_mma<<<grid, 128>>>(qkvh, cmb, ah);
    }
    // 4) proj GEMM -> fp32 out
    {
        dim3 grid(DIM_ / 128, MTOT / 128);
        gemm_h<float><<<grid, 256, gemm_smem>>>(ah, w2h, proj_b, out, DIM_, DIM_);
    }
}

// round 8
// speedup vs baseline: 1.0241x; 1.0241x over previous
#include <cuda_runtime.h>
#include <cuda_fp16.h>
#include <cstdint>

// Problem constants
#define BW_    1024
#define NTOK   64
#define DIM_   512
#define NH_    16
#define HD_    32
#define NW_    64
#define TRIPLE 1536
#define MTOT   (BW_ * NTOK)            /* 65536 */
#define SCALE_ 0.17677669529663687f

// ---------------------------------------------------------------------------
// Scratch (allocation-free rule: __device__ globals)
// ---------------------------------------------------------------------------
__device__ __half g_qkvh[(size_t)MTOT * TRIPLE];    // fp16 qkv (~201MB)
__device__ __half g_xh[(size_t)MTOT * DIM_];
__device__ __half g_ah[(size_t)MTOT * DIM_];
__device__ __half g_w1h[TRIPLE * DIM_];
__device__ __half g_w2h[DIM_ * DIM_];
__device__ float  g_b1[TRIPLE];                      // prescaled qkv bias
__device__ float  g_cmb[(size_t)NW_ * NH_ * NTOK * NTOK];  // bias+mask (16MB)

// ---------------------------------------------------------------------------
// helpers
// ---------------------------------------------------------------------------
__device__ __forceinline__ uint32_t smem_u32(const void* p) {
    uint32_t a;
    asm("{ .reg .u64 t; cvta.to.shared.u64 t, %1; cvt.u32.u64 %0, t; }"
        : "=r"(a) : "l"(p));
    return a;
}

#define CP_ASYNC16(smem_addr, gptr) \
    asm volatile("cp.async.cg.shared.global [%0], [%1], 16;" \
                 :: "r"((uint32_t)(smem_addr)), "l"(gptr) : "memory")
#define CP_ASYNC_COMMIT() asm volatile("cp.async.commit_group;" ::: "memory")
#define CP_ASYNC_WAIT0()  asm volatile("cp.async.wait_group 0;" ::: "memory")
#define CP_ASYNC_WAIT1()  asm volatile("cp.async.wait_group 1;" ::: "memory")

__device__ __forceinline__ void ldsm4(uint32_t* r, uint32_t addr) {
    asm volatile("ldmatrix.sync.aligned.m8n8.x4.shared.b16 {%0,%1,%2,%3}, [%4];"
                 : "=r"(r[0]), "=r"(r[1]), "=r"(r[2]), "=r"(r[3]) : "r"(addr));
}
__device__ __forceinline__ void ldsm4t(uint32_t* r, uint32_t addr) {
    asm volatile("ldmatrix.sync.aligned.m8n8.x4.trans.shared.b16 {%0,%1,%2,%3}, [%4];"
                 : "=r"(r[0]), "=r"(r[1]), "=r"(r[2]), "=r"(r[3]) : "r"(addr));
}

#define MMA_F16(d, a0, a1, a2, a3, b0, b1) \
    asm volatile("mma.sync.aligned.m16n8k16.row.col.f32.f16.f16.f32 " \
        "{%0,%1,%2,%3}, {%4,%5,%6,%7}, {%8,%9}, {%0,%1,%2,%3};" \
        : "+f"((d)[0]), "+f"((d)[1]), "+f"((d)[2]), "+f"((d)[3]) \
        : "r"(a0), "r"(a1), "r"(a2), "r"(a3), "r"(b0), "r"(b1))

// ---------------------------------------------------------------------------
// Prep kernels
// ---------------------------------------------------------------------------
__global__ __launch_bounds__(256) void convert_half(
    const float* __restrict__ in, __half* __restrict__ out, int n)
{
    int i = (blockIdx.x * 256 + threadIdx.x) * 4;
    if (i >= n) return;
    float4 v = *(const float4*)(in + i);
    __half h[4] = {__float2half(v.x), __float2half(v.y),
                   __float2half(v.z), __float2half(v.w)};
    *(uint2*)(out + i) = *(uint2*)h;
}

// qkv weight with Wq rows scaled by SCALE_
__global__ __launch_bounds__(256) void convert_w1(
    const float* __restrict__ in, __half* __restrict__ out)
{
    int i = (blockIdx.x * 256 + threadIdx.x) * 4;
    float sc = (i < 512 * 512) ? SCALE_ : 1.0f;
    float4 v = *(const float4*)(in + i);
    __half h[4] = {__float2half(v.x * sc), __float2half(v.y * sc),
                   __float2half(v.z * sc), __float2half(v.w * sc)};
    *(uint2*)(out + i) = *(uint2*)h;
}

__global__ __launch_bounds__(256) void prep_b1(
    const float* __restrict__ qkv_b, float* __restrict__ b1)
{
    int idx = blockIdx.x * 256 + threadIdx.x;
    if (idx < TRIPLE)
        b1[idx] = qkv_b[idx] * (idx < 512 ? SCALE_ : 1.0f);
}

// combined bias+mask: cmb[nw][h][i][j] = table[rel_index[ij]*16+h] + mask[nw][ij]
__global__ __launch_bounds__(256) void prep_cmb(
    const float* __restrict__ table, const int* __restrict__ rel_index,
    const float* __restrict__ mask, float* __restrict__ cmb)
{
    int t = blockIdx.x * 256 + threadIdx.x;       // over NW*NH*4096
    int ij = t & 4095;
    int h = (t >> 12) & 15;
    int nw = t >> 16;
    cmb[t] = table[rel_index[ij] * NH_ + h] + mask[(nw << 12) + ij];
}

// ---------------------------------------------------------------------------
// fp16 GEMM (NT) on mma.sync: C = A @ B^T + bias. Templated output type.
// CTA 128x128, BK=32, 256 thr (8 warps of 32x64), 3-stage cp.async.
// (Exact R5 mainloop — measured config for 2 CTAs/SM.)
// ---------------------------------------------------------------------------
#define ROWB 80
#define TILE_B (128 * ROWB)
#define STAGE_B (2 * TILE_B)
#define NSTAGE 3

template <typename OutT>
__global__ __launch_bounds__(256, 2)
void gemm_h(const __half* __restrict__ A, const __half* __restrict__ B,
            const float* __restrict__ bias, OutT* __restrict__ C,
            int Nn, int K)
{
    extern __shared__ char smem[];
    const uint32_t sbase = smem_u32(smem);

    const int tid  = threadIdx.x;
    const int lane = tid & 31;
    const int wid  = tid >> 5;
    const int wm   = (wid & 3) * 32;
    const int wn   = (wid >> 2) * 64;
    const int m0 = blockIdx.y * 128;
    const int n0 = blockIdx.x * 128;

    float acc[2][8][4];
    #pragma unroll
    for (int a = 0; a < 2; ++a)
        #pragma unroll
        for (int b = 0; b < 8; ++b)
            #pragma unroll
            for (int c = 0; c < 4; ++c) acc[a][b][c] = 0.f;

    const int nIter = K / 32;

    auto load_stage = [&](int s, int k0) {
        uint32_t st = sbase + s * STAGE_B;
        #pragma unroll
        for (int j = 0; j < 2; ++j) {
            int lin = tid + j * 256;
            int r = lin >> 2;
            int c = lin & 3;
            uint32_t dst = r * ROWB + c * 16;
            CP_ASYNC16(st + dst, A + (size_t)(m0 + r) * K + k0 + c * 8);
            CP_ASYNC16(st + TILE_B + dst, B + (size_t)(n0 + r) * K + k0 + c * 8);
        }
        CP_ASYNC_COMMIT();
    };

    load_stage(0, 0);
    load_stage(1, 32);

    const uint32_t a_row = wm + (lane & 15);
    const uint32_t a_k8  = (lane >> 4) * 8;
    const int g = lane >> 3;
    const uint32_t b_row = wn + (g >> 1) * 8 + (lane & 7);
    const uint32_t b_k8  = (g & 1) * 8;

    for (int it = 0; it < nIter; ++it) {
        if (it + 1 < nIter) { CP_ASYNC_WAIT1(); } else { CP_ASYNC_WAIT0(); }
        __syncthreads();
        if (it + 2 < nIter) load_stage((it + 2) % NSTAGE, (it + 2) * 32);

        uint32_t st = sbase + (it % NSTAGE) * STAGE_B;
        uint32_t sA = st, sB = st + TILE_B;

        #pragma unroll
        for (int ks = 0; ks < 2; ++ks) {
            uint32_t ah[2][4], bh[4][4];
            uint32_t akoff = (ks * 16 + a_k8) * 2;
            uint32_t bkoff = (ks * 16 + b_k8) * 2;
            #pragma unroll
            for (int mt = 0; mt < 2; ++mt)
                ldsm4(ah[mt], sA + (a_row + mt * 16) * ROWB + akoff);
            #pragma unroll
            for (int nt = 0; nt < 4; ++nt)
                ldsm4(bh[nt], sB + (b_row + nt * 16) * ROWB + bkoff);
            #pragma unroll
            for (int mt = 0; mt < 2; ++mt)
                #pragma unroll
                for (int nt = 0; nt < 8; ++nt) {
                    int q = nt >> 1, h = (nt & 1) * 2;
                    MMA_F16(acc[mt][nt], ah[mt][0], ah[mt][1], ah[mt][2],
                            ah[mt][3], bh[q][h], bh[q][h + 1]);
                }
        }
        __syncthreads();
    }

    #pragma unroll
    for (int mt = 0; mt < 2; ++mt) {
        int r0 = m0 + wm + mt * 16 + (lane >> 2);
        #pragma unroll
        for (int nt = 0; nt < 8; ++nt) {
            int col = n0 + wn + (nt >> 1) * 16 + (nt & 1) * 8 + (lane & 3) * 2;
            float b0 = __ldg(bias + col), b1 = __ldg(bias + col + 1);
            float v00 = acc[mt][nt][0] + b0, v01 = acc[mt][nt][1] + b1;
            float v10 = acc[mt][nt][2] + b0, v11 = acc[mt][nt][3] + b1;
            if (sizeof(OutT) == 2) {
                __half2 h0 = __floats2half2_rn(v00, v01);
                __half2 h1 = __floats2half2_rn(v10, v11);
                *(__half2*)((__half*)C + (size_t)r0 * Nn + col) = h0;
                *(__half2*)((__half*)C + (size_t)(r0 + 8) * Nn + col) = h1;
            } else {
                float2 f0 = {v00, v01}, f1 = {v10, v11};
                *(float2*)((float*)C + (size_t)r0 * Nn + col) = f0;
                *(float2*)((float*)C + (size_t)(r0 + 8) * Nn + col) = f1;
            }
        }
    }
}

// ---------------------------------------------------------------------------
// Attention via mma.sync: one block per (head, window), 4 warps.
// ---------------------------------------------------------------------------
#define AROWB 80   /* 32 halfs + pad */

__global__ __launch_bounds__(128) void attn_mma(
    const __half* __restrict__ qkv,      // (BW, N, 1536), Wq prescaled
    const float* __restrict__ cmb,       // (NW, NH, 64, 64) bias+mask
    __half* __restrict__ outh)           // (BW, N, DIM)
{
    const int h  = blockIdx.x;
    const int bw = blockIdx.y;
    const int tid = threadIdx.x;
    const int lane = tid & 31;
    const int wid = tid >> 5;

    __shared__ __align__(16) unsigned char sm[3 * 64 * AROWB];
    const uint32_t sbase = smem_u32(sm);
    const uint32_t sQ = sbase, sK = sbase + 64 * AROWB, sV = sbase + 2 * 64 * AROWB;

    // Load Q,K,V tiles (64x32 fp16 each) into padded smem.
    {
        const __half* src = qkv + (size_t)bw * NTOK * TRIPLE + h * HD_;
        #pragma unroll
        for (int t = 0; t < 6; ++t) {
            int lin = tid + t * 128;          // 0..767
            int m = lin >> 8;                 // 0=q 1=k 2=v
            int rem = lin & 255;
            int row = rem >> 2, c16 = rem & 3;
            uint4 val = *(const uint4*)(src + (size_t)row * TRIPLE + m * 512 + c16 * 8);
            *(uint4*)(sm + m * 64 * AROWB + row * AROWB + c16 * 16) = val;
        }
    }
    __syncthreads();

    // ---- Phase 1: S = Q @ K^T ----
    float s[8][4];
    #pragma unroll
    for (int nt = 0; nt < 8; ++nt)
        #pragma unroll
        for (int c = 0; c < 4; ++c) s[nt][c] = 0.f;

    const uint32_t a_row = wid * 16 + (lane & 15);
    const uint32_t a_k8  = (lane >> 4) * 8;
    const int g = lane >> 3;
    const uint32_t b_row = (g >> 1) * 8 + (lane & 7);
    const uint32_t b_k8  = (g & 1) * 8;

    #pragma unroll
    for (int ks = 0; ks < 2; ++ks) {
        uint32_t aq[4], bk[4][4];
        uint32_t akoff = (ks * 16 + a_k8) * 2;
        uint32_t bkoff = (ks * 16 + b_k8) * 2;
        ldsm4(aq, sQ + a_row * AROWB + akoff);
        #pragma unroll
        for (int nt = 0; nt < 4; ++nt)
            ldsm4(bk[nt], sK + (b_row + nt * 16) * AROWB + bkoff);
        #pragma unroll
        for (int nt = 0; nt < 8; ++nt) {
            int q = nt >> 1, hh = (nt & 1) * 2;
            MMA_F16(s[nt], aq[0], aq[1], aq[2], aq[3], bk[q][hh], bk[q][hh + 1]);
        }
    }

    // ---- combined bias+mask ----
    const int r = wid * 16 + (lane >> 2);
    const int cbase = (lane & 3) * 2;
    const float* crow = cmb + (((size_t)(bw & (NW_ - 1)) * NH_ + h) << 12);
    #pragma unroll
    for (int nt = 0; nt < 8; ++nt) {
        int c = nt * 8 + cbase;
        float2 c0 = *(const float2*)(crow + r * 64 + c);
        float2 c1 = *(const float2*)(crow + (r + 8) * 64 + c);
        s[nt][0] += c0.x; s[nt][1] += c0.y;
        s[nt][2] += c1.x; s[nt][3] += c1.y;
    }

    // ---- softmax over 64 cols (4 lanes per row) ----
    {
        float mx0 = -1e30f, mx1 = -1e30f;
        #pragma unroll
        for (int nt = 0; nt < 8; ++nt) {
            mx0 = fmaxf(mx0, fmaxf(s[nt][0], s[nt][1]));
            mx1 = fmaxf(mx1, fmaxf(s[nt][2], s[nt][3]));
        }
        #pragma unroll
        for (int o = 1; o <= 2; o <<= 1) {
            mx0 = fmaxf(mx0, __shfl_xor_sync(0xffffffffu, mx0, o));
            mx1 = fmaxf(mx1, __shfl_xor_sync(0xffffffffu, mx1, o));
        }
        float sm0 = 0.f, sm1 = 0.f;
        #pragma unroll
        for (int nt = 0; nt < 8; ++nt) {
            s[nt][0] = __expf(s[nt][0] - mx0); sm0 += s[nt][0];
            s[nt][1] = __expf(s[nt][1] - mx0); sm0 += s[nt][1];
            s[nt][2] = __expf(s[nt][2] - mx1); sm1 += s[nt][2];
            s[nt][3] = __expf(s[nt][3] - mx1); sm1 += s[nt][3];
        }
        #pragma unroll
        for (int o = 1; o <= 2; o <<= 1) {
            sm0 += __shfl_xor_sync(0xffffffffu, sm0, o);
            sm1 += __shfl_xor_sync(0xffffffffu, sm1, o);
        }
        float i0 = 1.f / sm0, i1 = 1.f / sm1;
        #pragma unroll
        for (int nt = 0; nt < 8; ++nt) {
            s[nt][0] *= i0; s[nt][1] *= i0;
            s[nt][2] *= i1; s[nt][3] *= i1;
        }
    }

    // ---- Phase 2: O = P @ V ----
    float o[4][4];
    #pragma unroll
    for (int nt = 0; nt < 4; ++nt)
        #pragma unroll
        for (int c = 0; c < 4; ++c) o[nt][c] = 0.f;

    const uint32_t v_row = lane & 15;
    const uint32_t v_c16 = (lane >> 4) * 16;
    #pragma unroll
    for (int kt = 0; kt < 4; ++kt) {
        __half2 pa0 = __floats2half2_rn(s[2 * kt][0], s[2 * kt][1]);
        __half2 pa1 = __floats2half2_rn(s[2 * kt][2], s[2 * kt][3]);
        __half2 pa2 = __floats2half2_rn(s[2 * kt + 1][0], s[2 * kt + 1][1]);
        __half2 pa3 = __floats2half2_rn(s[2 * kt + 1][2], s[2 * kt + 1][3]);
        uint32_t a0 = *(uint32_t*)&pa0, a1 = *(uint32_t*)&pa1;
        uint32_t a2 = *(uint32_t*)&pa2, a3 = *(uint32_t*)&pa3;
        uint32_t vb0[4], vb1[4];
        ldsm4t(vb0, sV + (kt * 16 + v_row) * AROWB + v_c16);
        ldsm4t(vb1, sV + (kt * 16 + v_row) * AROWB + 32 + v_c16);
        MMA_F16(o[0], a0, a1, a2, a3, vb0[0], vb0[1]);
        MMA_F16(o[1], a0, a1, a2, a3, vb0[2], vb0[3]);
        MMA_F16(o[2], a0, a1, a2, a3, vb1[0], vb1[1]);
        MMA_F16(o[3], a0, a1, a2, a3, vb1[2], vb1[3]);
    }

    // ---- write O (fp16) ----
    __half* obase = outh + (size_t)bw * NTOK * DIM_ + (size_t)h * HD_;
    #pragma unroll
    for (int nt = 0; nt < 4; ++nt) {
        int c = nt * 8 + cbase;
        __half2 h0 = __floats2half2_rn(o[nt][0], o[nt][1]);
        __half2 h1 = __floats2half2_rn(o[nt][2], o[nt][3]);
        *(__half2*)(obase + (size_t)r * DIM_ + c) = h0;
        *(__half2*)(obase + (size_t)(r + 8) * DIM_ + c) = h1;
    }
}

// ---------------------------------------------------------------------------
extern "C" void kernel_launch(void* const* d_in, const int* in_sizes, int n_in,
                              void* d_out, int out_size)
{
    const float* x       = (const float*)d_in[0];
    const float* mask    = (const float*)d_in[1];
    const float* qkv_w   = (const float*)d_in[2];
    const float* qkv_b   = (const float*)d_in[3];
    const float* table   = (const float*)d_in[4];
    const float* proj_w  = (const float*)d_in[5];
    const float* proj_b  = (const float*)d_in[6];
    const int*   rel_idx = (const int*)d_in[7];
    float* out = (float*)d_out;

    __half *qkvh, *xh, *ah, *w1h, *w2h;
    float *b1, *cmb;
    cudaGetSymbolAddress((void**)&qkvh, g_qkvh);
    cudaGetSymbolAddress((void**)&xh, g_xh);
    cudaGetSymbolAddress((void**)&ah, g_ah);
    cudaGetSymbolAddress((void**)&w1h, g_w1h);
    cudaGetSymbolAddress((void**)&w2h, g_w2h);
    cudaGetSymbolAddress((void**)&b1, g_b1);
    cudaGetSymbolAddress((void**)&cmb, g_cmb);

    const int gemm_smem = NSTAGE * STAGE_B;   // 61440
    cudaFuncSetAttribute(gemm_h<__half>, cudaFuncAttributeMaxDynamicSharedMemorySize,
                         gemm_smem);
    cudaFuncSetAttribute(gemm_h<float>, cudaFuncAttributeMaxDynamicSharedMemorySize,
                         gemm_smem);

    // 1) prep
    {
        int n1 = MTOT * DIM_;
        convert_half<<<n1 / 4 / 256, 256>>>(x, xh, n1);
        convert_w1<<<TRIPLE * DIM_ / 4 / 256, 256>>>(qkv_w, w1h);
        int n3 = DIM_ * DIM_;
        convert_half<<<n3 / 4 / 256, 256>>>(proj_w, w2h, n3);
        prep_b1<<<(TRIPLE + 255) / 256, 256>>>(qkv_b, b1);
        prep_cmb<<<NW_ * NH_ * NTOK * NTOK / 256, 256>>>(table, rel_idx, mask, cmb);
    }
    // 2) QKV GEMM -> fp16 qkv
    {
        dim3 grid(TRIPLE / 128, MTOT / 128);
        gemm_h<__half><<<grid, 256, gemm_smem>>>(xh, w1h, b1, qkvh, TRIPLE, DIM_);
    }
    // 3) attention (tensor-core)
    {
        dim3 grid(NH_, BW_);
        attn_mma<<<grid, 128>>>(qkvh, cmb, ah);
    }
    // 4) proj GEMM -> fp32 out
    {
        dim3 grid(DIM_ / 128, MTOT / 128);
        gemm_h<float><<<grid, 256, gemm_smem>>>(ah, w2h, proj_b, out, DIM_, DIM_);
    }
}

// round 9
// speedup vs baseline: 1.4937x; 1.4586x over previous
#include <cuda_runtime.h>
#include <cuda_fp16.h>
#include <cstdint>

// Problem constants
#define BW_    1024
#define NTOK   64
#define DIM_   512
#define NH_    16
#define HD_    32
#define NW_    64
#define TRIPLE 1536
#define MTOT   (BW_ * NTOK)            /* 65536 */
#define SCALE_ 0.17677669529663687f

// ---------------------------------------------------------------------------
// Scratch (allocation-free rule: __device__ globals)
// ---------------------------------------------------------------------------
__device__ __half g_qkvh[(size_t)MTOT * TRIPLE];    // fp16 qkv (~201MB)
__device__ __half g_xh[(size_t)MTOT * DIM_];
__device__ __half g_ah[(size_t)MTOT * DIM_];
__device__ __half g_w1h[TRIPLE * DIM_];
__device__ __half g_w2h[DIM_ * DIM_];
__device__ float  g_b1[TRIPLE];                      // prescaled qkv bias
__device__ float  g_bias[NH_ * NTOK * NTOK];         // gathered rel bias

// ---------------------------------------------------------------------------
// helpers
// ---------------------------------------------------------------------------
__device__ __forceinline__ uint32_t smem_u32(const void* p) {
    uint32_t a;
    asm("{ .reg .u64 t; cvta.to.shared.u64 t, %1; cvt.u32.u64 %0, t; }"
        : "=r"(a) : "l"(p));
    return a;
}

#define CP_ASYNC16(smem_addr, gptr) \
    asm volatile("cp.async.cg.shared.global [%0], [%1], 16;" \
                 :: "r"((uint32_t)(smem_addr)), "l"(gptr) : "memory")
#define CP_ASYNC_COMMIT() asm volatile("cp.async.commit_group;" ::: "memory")
#define CP_ASYNC_WAIT0()  asm volatile("cp.async.wait_group 0;" ::: "memory")
#define CP_ASYNC_WAIT1()  asm volatile("cp.async.wait_group 1;" ::: "memory")

__device__ __forceinline__ void ldsm4(uint32_t* r, uint32_t addr) {
    asm volatile("ldmatrix.sync.aligned.m8n8.x4.shared.b16 {%0,%1,%2,%3}, [%4];"
                 : "=r"(r[0]), "=r"(r[1]), "=r"(r[2]), "=r"(r[3]) : "r"(addr));
}
__device__ __forceinline__ void ldsm4t(uint32_t* r, uint32_t addr) {
    asm volatile("ldmatrix.sync.aligned.m8n8.x4.trans.shared.b16 {%0,%1,%2,%3}, [%4];"
                 : "=r"(r[0]), "=r"(r[1]), "=r"(r[2]), "=r"(r[3]) : "r"(addr));
}

#define MMA_F16(d, a0, a1, a2, a3, b0, b1) \
    asm volatile("mma.sync.aligned.m16n8k16.row.col.f32.f16.f16.f32 " \
        "{%0,%1,%2,%3}, {%4,%5,%6,%7}, {%8,%9}, {%0,%1,%2,%3};" \
        : "+f"((d)[0]), "+f"((d)[1]), "+f"((d)[2]), "+f"((d)[3]) \
        : "r"(a0), "r"(a1), "r"(a2), "r"(a3), "r"(b0), "r"(b1))

// ---------------------------------------------------------------------------
// Prep kernels
// ---------------------------------------------------------------------------
__global__ __launch_bounds__(256) void convert_half(
    const float* __restrict__ in, __half* __restrict__ out, int n)
{
    int i = (blockIdx.x * 256 + threadIdx.x) * 4;
    if (i >= n) return;
    float4 v = *(const float4*)(in + i);
    __half h[4] = {__float2half(v.x), __float2half(v.y),
                   __float2half(v.z), __float2half(v.w)};
    *(uint2*)(out + i) = *(uint2*)h;
}

// qkv weight with Wq rows scaled by SCALE_
__global__ __launch_bounds__(256) void convert_w1(
    const float* __restrict__ in, __half* __restrict__ out)
{
    int i = (blockIdx.x * 256 + threadIdx.x) * 4;
    float sc = (i < 512 * 512) ? SCALE_ : 1.0f;
    float4 v = *(const float4*)(in + i);
    __half h[4] = {__float2half(v.x * sc), __float2half(v.y * sc),
                   __float2half(v.z * sc), __float2half(v.w * sc)};
    *(uint2*)(out + i) = *(uint2*)h;
}

__global__ __launch_bounds__(256) void prep_misc(
    const float* __restrict__ qkv_b, float* __restrict__ b1,
    const float* __restrict__ table, const int* __restrict__ rel_index,
    float* __restrict__ bias)
{
    int idx = blockIdx.x * 256 + threadIdx.x;
    if (idx < TRIPLE)
        b1[idx] = qkv_b[idx] * (idx < 512 ? SCALE_ : 1.0f);
    // bias gather: 16 heads x 4096
    for (int t = idx; t < NH_ * NTOK * NTOK; t += gridDim.x * 256) {
        int h = t >> 12, ij = t & 4095;
        bias[t] = table[rel_index[ij] * NH_ + h];
    }
}

// ---------------------------------------------------------------------------
// fp16 GEMM (NT) on mma.sync: C = A @ B^T + bias. Templated output type.
// CTA 128x128, BK=32, 256 thr (8 warps of 32x64), 3-stage cp.async.
// ---------------------------------------------------------------------------
#define ROWB 80
#define TILE_B (128 * ROWB)
#define STAGE_B (2 * TILE_B)
#define NSTAGE 3

template <typename OutT>
__global__ __launch_bounds__(256, 2)
void gemm_h(const __half* __restrict__ A, const __half* __restrict__ B,
            const float* __restrict__ bias, OutT* __restrict__ C,
            int Nn, int K)
{
    extern __shared__ char smem[];
    const uint32_t sbase = smem_u32(smem);

    const int tid  = threadIdx.x;
    const int lane = tid & 31;
    const int wid  = tid >> 5;
    const int wm   = (wid & 3) * 32;
    const int wn   = (wid >> 2) * 64;
    const int m0 = blockIdx.y * 128;
    const int n0 = blockIdx.x * 128;

    float acc[2][8][4];
    #pragma unroll
    for (int a = 0; a < 2; ++a)
        #pragma unroll
        for (int b = 0; b < 8; ++b)
            #pragma unroll
            for (int c = 0; c < 4; ++c) acc[a][b][c] = 0.f;

    const int nIter = K / 32;

    auto load_stage = [&](int s, int k0) {
        uint32_t st = sbase + s * STAGE_B;
        #pragma unroll
        for (int j = 0; j < 2; ++j) {
            int lin = tid + j * 256;
            int r = lin >> 2;
            int c = lin & 3;
            uint32_t dst = r * ROWB + c * 16;
            CP_ASYNC16(st + dst, A + (size_t)(m0 + r) * K + k0 + c * 8);
            CP_ASYNC16(st + TILE_B + dst, B + (size_t)(n0 + r) * K + k0 + c * 8);
        }
        CP_ASYNC_COMMIT();
    };

    load_stage(0, 0);
    load_stage(1, 32);

    const uint32_t a_row = wm + (lane & 15);
    const uint32_t a_k8  = (lane >> 4) * 8;
    const int g = lane >> 3;
    const uint32_t b_row = wn + (g >> 1) * 8 + (lane & 7);
    const uint32_t b_k8  = (g & 1) * 8;

    for (int it = 0; it < nIter; ++it) {
        if (it + 1 < nIter) { CP_ASYNC_WAIT1(); } else { CP_ASYNC_WAIT0(); }
        __syncthreads();
        if (it + 2 < nIter) load_stage((it + 2) % NSTAGE, (it + 2) * 32);

        uint32_t st = sbase + (it % NSTAGE) * STAGE_B;
        uint32_t sA = st, sB = st + TILE_B;

        #pragma unroll
        for (int ks = 0; ks < 2; ++ks) {
            uint32_t ah[2][4], bh[4][4];
            uint32_t akoff = (ks * 16 + a_k8) * 2;
            uint32_t bkoff = (ks * 16 + b_k8) * 2;
            #pragma unroll
            for (int mt = 0; mt < 2; ++mt)
                ldsm4(ah[mt], sA + (a_row + mt * 16) * ROWB + akoff);
            #pragma unroll
            for (int nt = 0; nt < 4; ++nt)
                ldsm4(bh[nt], sB + (b_row + nt * 16) * ROWB + bkoff);
            #pragma unroll
            for (int mt = 0; mt < 2; ++mt)
                #pragma unroll
                for (int nt = 0; nt < 8; ++nt) {
                    int q = nt >> 1, h = (nt & 1) * 2;
                    MMA_F16(acc[mt][nt], ah[mt][0], ah[mt][1], ah[mt][2],
                            ah[mt][3], bh[q][h], bh[q][h + 1]);
                }
        }
        __syncthreads();
    }

    #pragma unroll
    for (int mt = 0; mt < 2; ++mt) {
        int r0 = m0 + wm + mt * 16 + (lane >> 2);
        #pragma unroll
        for (int nt = 0; nt < 8; ++nt) {
            int col = n0 + wn + (nt >> 1) * 16 + (nt & 1) * 8 + (lane & 3) * 2;
            float b0 = __ldg(bias + col), b1 = __ldg(bias + col + 1);
            float v00 = acc[mt][nt][0] + b0, v01 = acc[mt][nt][1] + b1;
            float v10 = acc[mt][nt][2] + b0, v11 = acc[mt][nt][3] + b1;
            if (sizeof(OutT) == 2) {
                __half2 h0 = __floats2half2_rn(v00, v01);
                __half2 h1 = __floats2half2_rn(v10, v11);
                *(__half2*)((__half*)C + (size_t)r0 * Nn + col) = h0;
                *(__half2*)((__half*)C + (size_t)(r0 + 8) * Nn + col) = h1;
            } else {
                float2 f0 = {v00, v01}, f1 = {v10, v11};
                *(float2*)((float*)C + (size_t)r0 * Nn + col) = f0;
                *(float2*)((float*)C + (size_t)(r0 + 8) * Nn + col) = f1;
            }
        }
    }
}

// ---------------------------------------------------------------------------
// Attention via mma.sync: one block per (head, window), 4 warps.
// ---------------------------------------------------------------------------
#define AROWB 80   /* 32 halfs + pad */

__global__ __launch_bounds__(128) void attn_mma(
    const __half* __restrict__ qkv,      // (BW, N, 1536), Wq prescaled
    const float* __restrict__ mask,      // (NW, 64, 64)
    const float* __restrict__ bias,      // (NH, 64, 64)
    __half* __restrict__ outh)           // (BW, N, DIM)
{
    const int h  = blockIdx.x;
    const int bw = blockIdx.y;
    const int tid = threadIdx.x;
    const int lane = tid & 31;
    const int wid = tid >> 5;

    __shared__ __align__(16) unsigned char sm[3 * 64 * AROWB];
    const uint32_t sbase = smem_u32(sm);
    const uint32_t sQ = sbase, sK = sbase + 64 * AROWB, sV = sbase + 2 * 64 * AROWB;

    // Load Q,K,V tiles (64x32 fp16 each) into padded smem.
    {
        const __half* src = qkv + (size_t)bw * NTOK * TRIPLE + h * HD_;
        #pragma unroll
        for (int t = 0; t < 6; ++t) {
            int lin = tid + t * 128;          // 0..767
            int m = lin >> 8;                 // 0=q 1=k 2=v
            int rem = lin & 255;
            int row = rem >> 2, c16 = rem & 3;
            uint4 val = *(const uint4*)(src + (size_t)row * TRIPLE + m * 512 + c16 * 8);
            *(uint4*)(sm + m * 64 * AROWB + row * AROWB + c16 * 16) = val;
        }
    }
    __syncthreads();

    // ---- Phase 1: S = Q @ K^T ----
    float s[8][4];
    #pragma unroll
    for (int nt = 0; nt < 8; ++nt)
        #pragma unroll
        for (int c = 0; c < 4; ++c) s[nt][c] = 0.f;

    const uint32_t a_row = wid * 16 + (lane & 15);
    const uint32_t a_k8  = (lane >> 4) * 8;
    const int g = lane >> 3;
    const uint32_t b_row = (g >> 1) * 8 + (lane & 7);
    const uint32_t b_k8  = (g & 1) * 8;

    #pragma unroll
    for (int ks = 0; ks < 2; ++ks) {
        uint32_t aq[4], bk[4][4];
        uint32_t akoff = (ks * 16 + a_k8) * 2;
        uint32_t bkoff = (ks * 16 + b_k8) * 2;
        ldsm4(aq, sQ + a_row * AROWB + akoff);
        #pragma unroll
        for (int nt = 0; nt < 4; ++nt)
            ldsm4(bk[nt], sK + (b_row + nt * 16) * AROWB + bkoff);
        #pragma unroll
        for (int nt = 0; nt < 8; ++nt) {
            int q = nt >> 1, hh = (nt & 1) * 2;
            MMA_F16(s[nt], aq[0], aq[1], aq[2], aq[3], bk[q][hh], bk[q][hh + 1]);
        }
    }

    // ---- bias + mask ----
    const int r = wid * 16 + (lane >> 2);
    const int cbase = (lane & 3) * 2;
    const float* brow = bias + ((size_t)h << 12);
    const float* mrow = mask + ((size_t)(bw & (NW_ - 1)) << 12);
    #pragma unroll
    for (int nt = 0; nt < 8; ++nt) {
        int c = nt * 8 + cbase;
        float2 b0 = *(const float2*)(brow + r * 64 + c);
        float2 m0 = *(const float2*)(mrow + r * 64 + c);
        float2 b1 = *(const float2*)(brow + (r + 8) * 64 + c);
        float2 m1 = *(const float2*)(mrow + (r + 8) * 64 + c);
        s[nt][0] += b0.x + m0.x; s[nt][1] += b0.y + m0.y;
        s[nt][2] += b1.x + m1.x; s[nt][3] += b1.y + m1.y;
    }

    // ---- softmax over 64 cols (4 lanes per row) ----
    {
        float mx0 = -1e30f, mx1 = -1e30f;
        #pragma unroll
        for (int nt = 0; nt < 8; ++nt) {
            mx0 = fmaxf(mx0, fmaxf(s[nt][0], s[nt][1]));
            mx1 = fmaxf(mx1, fmaxf(s[nt][2], s[nt][3]));
        }
        #pragma unroll
        for (int o = 1; o <= 2; o <<= 1) {
            mx0 = fmaxf(mx0, __shfl_xor_sync(0xffffffffu, mx0, o));
            mx1 = fmaxf(mx1, __shfl_xor_sync(0xffffffffu, mx1, o));
        }
        float sm0 = 0.f, sm1 = 0.f;
        #pragma unroll
        for (int nt = 0; nt < 8; ++nt) {
            s[nt][0] = __expf(s[nt][0] - mx0); sm0 += s[nt][0];
            s[nt][1] = __expf(s[nt][1] - mx0); sm0 += s[nt][1];
            s[nt][2] = __expf(s[nt][2] - mx1); sm1 += s[nt][2];
            s[nt][3] = __expf(s[nt][3] - mx1); sm1 += s[nt][3];
        }
        #pragma unroll
        for (int o = 1; o <= 2; o <<= 1) {
            sm0 += __shfl_xor_sync(0xffffffffu, sm0, o);
            sm1 += __shfl_xor_sync(0xffffffffu, sm1, o);
        }
        float i0 = 1.f / sm0, i1 = 1.f / sm1;
        #pragma unroll
        for (int nt = 0; nt < 8; ++nt) {
            s[nt][0] *= i0; s[nt][1] *= i0;
            s[nt][2] *= i1; s[nt][3] *= i1;
        }
    }

    // ---- Phase 2: O = P @ V ----
    float o[4][4];
    #pragma unroll
    for (int nt = 0; nt < 4; ++nt)
        #pragma unroll
        for (int c = 0; c < 4; ++c) o[nt][c] = 0.f;

    const uint32_t v_row = lane & 15;
    const uint32_t v_c16 = (lane >> 4) * 16;
    #pragma unroll
    for (int kt = 0; kt < 4; ++kt) {
        __half2 pa0 = __floats2half2_rn(s[2 * kt][0], s[2 * kt][1]);
        __half2 pa1 = __floats2half2_rn(s[2 * kt][2], s[2 * kt][3]);
        __half2 pa2 = __floats2half2_rn(s[2 * kt + 1][0], s[2 * kt + 1][1]);
        __half2 pa3 = __floats2half2_rn(s[2 * kt + 1][2], s[2 * kt + 1][3]);
        uint32_t a0 = *(uint32_t*)&pa0, a1 = *(uint32_t*)&pa1;
        uint32_t a2 = *(uint32_t*)&pa2, a3 = *(uint32_t*)&pa3;
        uint32_t vb0[4], vb1[4];
        ldsm4t(vb0, sV + (kt * 16 + v_row) * AROWB + v_c16);
        ldsm4t(vb1, sV + (kt * 16 + v_row) * AROWB + 32 + v_c16);
        MMA_F16(o[0], a0, a1, a2, a3, vb0[0], vb0[1]);
        MMA_F16(o[1], a0, a1, a2, a3, vb0[2], vb0[3]);
        MMA_F16(o[2], a0, a1, a2, a3, vb1[0], vb1[1]);
        MMA_F16(o[3], a0, a1, a2, a3, vb1[2], vb1[3]);
    }

    // ---- write O (fp16) ----
    __half* obase = outh + (size_t)bw * NTOK * DIM_ + (size_t)h * HD_;
    #pragma unroll
    for (int nt = 0; nt < 4; ++nt) {
        int c = nt * 8 + cbase;
        __half2 h0 = __floats2half2_rn(o[nt][0], o[nt][1]);
        __half2 h1 = __floats2half2_rn(o[nt][2], o[nt][3]);
        *(__half2*)(obase + (size_t)r * DIM_ + c) = h0;
        *(__half2*)(obase + (size_t)(r + 8) * DIM_ + c) = h1;
    }
}

// ---------------------------------------------------------------------------
extern "C" void kernel_launch(void* const* d_in, const int* in_sizes, int n_in,
                              void* d_out, int out_size)
{
    const float* x       = (const float*)d_in[0];
    const float* mask    = (const float*)d_in[1];
    const float* qkv_w   = (const float*)d_in[2];
    const float* qkv_b   = (const float*)d_in[3];
    const float* table   = (const float*)d_in[4];
    const float* proj_w  = (const float*)d_in[5];
    const float* proj_b  = (const float*)d_in[6];
    const int*   rel_idx = (const int*)d_in[7];
    float* out = (float*)d_out;

    __half *qkvh, *xh, *ah, *w1h, *w2h;
    float *b1, *bias;
    cudaGetSymbolAddress((void**)&qkvh, g_qkvh);
    cudaGetSymbolAddress((void**)&xh, g_xh);
    cudaGetSymbolAddress((void**)&ah, g_ah);
    cudaGetSymbolAddress((void**)&w1h, g_w1h);
    cudaGetSymbolAddress((void**)&w2h, g_w2h);
    cudaGetSymbolAddress((void**)&b1, g_b1);
    cudaGetSymbolAddress((void**)&bias, g_bias);

    const int gemm_smem = NSTAGE * STAGE_B;   // 61440
    cudaFuncSetAttribute(gemm_h<__half>, cudaFuncAttributeMaxDynamicSharedMemorySize,
                         gemm_smem);
    cudaFuncSetAttribute(gemm_h<float>, cudaFuncAttributeMaxDynamicSharedMemorySize,
                         gemm_smem);

    // 1) prep
    {
        int n1 = MTOT * DIM_;
        convert_half<<<n1 / 4 / 256, 256>>>(x, xh, n1);
        convert_w1<<<TRIPLE * DIM_ / 4 / 256, 256>>>(qkv_w, w1h);
        int n3 = DIM_ * DIM_;
        convert_half<<<n3 / 4 / 256, 256>>>(proj_w, w2h, n3);
        prep_misc<<<64, 256>>>(qkv_b, b1, table, rel_idx, bias);
    }
    // 2) QKV GEMM -> fp16 qkv
    {
        dim3 grid(TRIPLE / 128, MTOT / 128);
        gemm_h<__half><<<grid, 256, gemm_smem>>>(xh, w1h, b1, qkvh, TRIPLE, DIM_);
    }
    // 3) attention (tensor-core)
    {
        dim3 grid(NH_, BW_);
        attn_mma<<<grid, 128>>>(qkvh, mask, bias, ah);
    }
    // 4) proj GEMM -> fp32 out
    {
        dim3 grid(DIM_ / 128, MTOT / 128);
        gemm_h<float><<<grid, 256, gemm_smem>>>(ah, w2h, proj_b, out, DIM_, DIM_);
    }
}

// round 10
// speedup vs baseline: 1.4983x; 1.0031x over previous
#include <cuda_runtime.h>
#include <cuda_fp16.h>
#include <cstdint>

// Problem constants
#define BW_    1024
#define NTOK   64
#define DIM_   512
#define NH_    16
#define HD_    32
#define NW_    64
#define TRIPLE 1536
#define MTOT   (BW_ * NTOK)            /* 65536 */
#define SCALE_ 0.17677669529663687f

// ---------------------------------------------------------------------------
// Scratch (allocation-free rule: __device__ globals)
// ---------------------------------------------------------------------------
__device__ __half g_qkvh[(size_t)MTOT * TRIPLE];    // fp16 qkv (~201MB)
__device__ __half g_xh[(size_t)MTOT * DIM_];
__device__ __half g_ah[(size_t)MTOT * DIM_];
__device__ __half g_w1h[TRIPLE * DIM_];
__device__ __half g_w2h[DIM_ * DIM_];
__device__ float  g_b1[TRIPLE];                      // prescaled qkv bias
__device__ float  g_bias[NH_ * NTOK * NTOK];         // gathered rel bias

// ---------------------------------------------------------------------------
// helpers
// ---------------------------------------------------------------------------
__device__ __forceinline__ uint32_t smem_u32(const void* p) {
    uint32_t a;
    asm("{ .reg .u64 t; cvta.to.shared.u64 t, %1; cvt.u32.u64 %0, t; }"
        : "=r"(a) : "l"(p));
    return a;
}

#define CP_ASYNC16(smem_addr, gptr) \
    asm volatile("cp.async.cg.shared.global [%0], [%1], 16;" \
                 :: "r"((uint32_t)(smem_addr)), "l"(gptr) : "memory")
#define CP_ASYNC_COMMIT() asm volatile("cp.async.commit_group;" ::: "memory")
#define CP_ASYNC_WAIT0()  asm volatile("cp.async.wait_group 0;" ::: "memory")
#define CP_ASYNC_WAIT1()  asm volatile("cp.async.wait_group 1;" ::: "memory")

__device__ __forceinline__ void ldsm4(uint32_t* r, uint32_t addr) {
    asm volatile("ldmatrix.sync.aligned.m8n8.x4.shared.b16 {%0,%1,%2,%3}, [%4];"
                 : "=r"(r[0]), "=r"(r[1]), "=r"(r[2]), "=r"(r[3]) : "r"(addr));
}
__device__ __forceinline__ void ldsm4t(uint32_t* r, uint32_t addr) {
    asm volatile("ldmatrix.sync.aligned.m8n8.x4.trans.shared.b16 {%0,%1,%2,%3}, [%4];"
                 : "=r"(r[0]), "=r"(r[1]), "=r"(r[2]), "=r"(r[3]) : "r"(addr));
}

#define MMA_F16(d, a0, a1, a2, a3, b0, b1) \
    asm volatile("mma.sync.aligned.m16n8k16.row.col.f32.f16.f16.f32 " \
        "{%0,%1,%2,%3}, {%4,%5,%6,%7}, {%8,%9}, {%0,%1,%2,%3};" \
        : "+f"((d)[0]), "+f"((d)[1]), "+f"((d)[2]), "+f"((d)[3]) \
        : "r"(a0), "r"(a1), "r"(a2), "r"(a3), "r"(b0), "r"(b1))

// ---------------------------------------------------------------------------
// Prep kernels
// ---------------------------------------------------------------------------
__global__ __launch_bounds__(256) void convert_half(
    const float* __restrict__ in, __half* __restrict__ out, int n)
{
    int i = (blockIdx.x * 256 + threadIdx.x) * 4;
    if (i >= n) return;
    float4 v = *(const float4*)(in + i);
    __half h[4] = {__float2half(v.x), __float2half(v.y),
                   __float2half(v.z), __float2half(v.w)};
    *(uint2*)(out + i) = *(uint2*)h;
}

// qkv weight with Wq rows scaled by SCALE_
__global__ __launch_bounds__(256) void convert_w1(
    const float* __restrict__ in, __half* __restrict__ out)
{
    int i = (blockIdx.x * 256 + threadIdx.x) * 4;
    float sc = (i < 512 * 512) ? SCALE_ : 1.0f;
    float4 v = *(const float4*)(in + i);
    __half h[4] = {__float2half(v.x * sc), __float2half(v.y * sc),
                   __float2half(v.z * sc), __float2half(v.w * sc)};
    *(uint2*)(out + i) = *(uint2*)h;
}

__global__ __launch_bounds__(256) void prep_misc(
    const float* __restrict__ qkv_b, float* __restrict__ b1,
    const float* __restrict__ table, const int* __restrict__ rel_index,
    float* __restrict__ bias)
{
    int idx = blockIdx.x * 256 + threadIdx.x;
    if (idx < TRIPLE)
        b1[idx] = qkv_b[idx] * (idx < 512 ? SCALE_ : 1.0f);
    // bias gather: 16 heads x 4096
    for (int t = idx; t < NH_ * NTOK * NTOK; t += gridDim.x * 256) {
        int h = t >> 12, ij = t & 4095;
        bias[t] = table[rel_index[ij] * NH_ + h];
    }
}

// ---------------------------------------------------------------------------
// fp16 GEMM (NT) on mma.sync: C = A @ B^T + bias. Templated output type.
// CTA 128x128, BK=32, 256 thr (8 warps of 32x64), 3-stage cp.async.
// Trailing per-iter __syncthreads removed: the leading wait+sync already
// orders compute(it-1) before the load that overwrites stage (it+2)%3.
// ---------------------------------------------------------------------------
#define ROWB 80
#define TILE_B (128 * ROWB)
#define STAGE_B (2 * TILE_B)
#define NSTAGE 3

template <typename OutT>
__global__ __launch_bounds__(256, 2)
void gemm_h(const __half* __restrict__ A, const __half* __restrict__ B,
            const float* __restrict__ bias, OutT* __restrict__ C,
            int Nn, int K)
{
    extern __shared__ char smem[];
    const uint32_t sbase = smem_u32(smem);

    const int tid  = threadIdx.x;
    const int lane = tid & 31;
    const int wid  = tid >> 5;
    const int wm   = (wid & 3) * 32;
    const int wn   = (wid >> 2) * 64;
    const int m0 = blockIdx.y * 128;
    const int n0 = blockIdx.x * 128;

    float acc[2][8][4];
    #pragma unroll
    for (int a = 0; a < 2; ++a)
        #pragma unroll
        for (int b = 0; b < 8; ++b)
            #pragma unroll
            for (int c = 0; c < 4; ++c) acc[a][b][c] = 0.f;

    const int nIter = K / 32;

    auto load_stage = [&](int s, int k0) {
        uint32_t st = sbase + s * STAGE_B;
        #pragma unroll
        for (int j = 0; j < 2; ++j) {
            int lin = tid + j * 256;
            int r = lin >> 2;
            int c = lin & 3;
            uint32_t dst = r * ROWB + c * 16;
            CP_ASYNC16(st + dst, A + (size_t)(m0 + r) * K + k0 + c * 8);
            CP_ASYNC16(st + TILE_B + dst, B + (size_t)(n0 + r) * K + k0 + c * 8);
        }
        CP_ASYNC_COMMIT();
    };

    load_stage(0, 0);
    load_stage(1, 32);

    const uint32_t a_row = wm + (lane & 15);
    const uint32_t a_k8  = (lane >> 4) * 8;
    const int g = lane >> 3;
    const uint32_t b_row = wn + (g >> 1) * 8 + (lane & 7);
    const uint32_t b_k8  = (g & 1) * 8;

    for (int it = 0; it < nIter; ++it) {
        if (it + 1 < nIter) { CP_ASYNC_WAIT1(); } else { CP_ASYNC_WAIT0(); }
        __syncthreads();
        if (it + 2 < nIter) load_stage((it + 2) % NSTAGE, (it + 2) * 32);

        uint32_t st = sbase + (it % NSTAGE) * STAGE_B;
        uint32_t sA = st, sB = st + TILE_B;

        #pragma unroll
        for (int ks = 0; ks < 2; ++ks) {
            uint32_t ah[2][4], bh[4][4];
            uint32_t akoff = (ks * 16 + a_k8) * 2;
            uint32_t bkoff = (ks * 16 + b_k8) * 2;
            #pragma unroll
            for (int mt = 0; mt < 2; ++mt)
                ldsm4(ah[mt], sA + (a_row + mt * 16) * ROWB + akoff);
            #pragma unroll
            for (int nt = 0; nt < 4; ++nt)
                ldsm4(bh[nt], sB + (b_row + nt * 16) * ROWB + bkoff);
            #pragma unroll
            for (int mt = 0; mt < 2; ++mt)
                #pragma unroll
                for (int nt = 0; nt < 8; ++nt) {
                    int q = nt >> 1, h = (nt & 1) * 2;
                    MMA_F16(acc[mt][nt], ah[mt][0], ah[mt][1], ah[mt][2],
                            ah[mt][3], bh[q][h], bh[q][h + 1]);
                }
        }
        // no trailing __syncthreads: next iteration's leading barrier is
        // sequenced before the only load that can overwrite this stage.
    }

    #pragma unroll
    for (int mt = 0; mt < 2; ++mt) {
        int r0 = m0 + wm + mt * 16 + (lane >> 2);
        #pragma unroll
        for (int nt = 0; nt < 8; ++nt) {
            int col = n0 + wn + (nt >> 1) * 16 + (nt & 1) * 8 + (lane & 3) * 2;
            float b0 = __ldg(bias + col), b1 = __ldg(bias + col + 1);
            float v00 = acc[mt][nt][0] + b0, v01 = acc[mt][nt][1] + b1;
            float v10 = acc[mt][nt][2] + b0, v11 = acc[mt][nt][3] + b1;
            if (sizeof(OutT) == 2) {
                __half2 h0 = __floats2half2_rn(v00, v01);
                __half2 h1 = __floats2half2_rn(v10, v11);
                *(__half2*)((__half*)C + (size_t)r0 * Nn + col) = h0;
                *(__half2*)((__half*)C + (size_t)(r0 + 8) * Nn + col) = h1;
            } else {
                float2 f0 = {v00, v01}, f1 = {v10, v11};
                *(float2*)((float*)C + (size_t)r0 * Nn + col) = f0;
                *(float2*)((float*)C + (size_t)(r0 + 8) * Nn + col) = f1;
            }
        }
    }
}

// ---------------------------------------------------------------------------
// Attention via mma.sync: one block per (head, window), 4 warps.
// ---------------------------------------------------------------------------
#define AROWB 80   /* 32 halfs + pad */

__global__ __launch_bounds__(128) void attn_mma(
    const __half* __restrict__ qkv,      // (BW, N, 1536), Wq prescaled
    const float* __restrict__ mask,      // (NW, 64, 64)
    const float* __restrict__ bias,      // (NH, 64, 64)
    __half* __restrict__ outh)           // (BW, N, DIM)
{
    const int h  = blockIdx.x;
    const int bw = blockIdx.y;
    const int tid = threadIdx.x;
    const int lane = tid & 31;
    const int wid = tid >> 5;

    __shared__ __align__(16) unsigned char sm[3 * 64 * AROWB];
    const uint32_t sbase = smem_u32(sm);
    const uint32_t sQ = sbase, sK = sbase + 64 * AROWB, sV = sbase + 2 * 64 * AROWB;

    // Load Q,K,V tiles (64x32 fp16 each) into padded smem.
    {
        const __half* src = qkv + (size_t)bw * NTOK * TRIPLE + h * HD_;
        #pragma unroll
        for (int t = 0; t < 6; ++t) {
            int lin = tid + t * 128;          // 0..767
            int m = lin >> 8;                 // 0=q 1=k 2=v
            int rem = lin & 255;
            int row = rem >> 2, c16 = rem & 3;
            uint4 val = *(const uint4*)(src + (size_t)row * TRIPLE + m * 512 + c16 * 8);
            *(uint4*)(sm + m * 64 * AROWB + row * AROWB + c16 * 16) = val;
        }
    }
    __syncthreads();

    // ---- Phase 1: S = Q @ K^T ----
    float s[8][4];
    #pragma unroll
    for (int nt = 0; nt < 8; ++nt)
        #pragma unroll
        for (int c = 0; c < 4; ++c) s[nt][c] = 0.f;

    const uint32_t a_row = wid * 16 + (lane & 15);
    const uint32_t a_k8  = (lane >> 4) * 8;
    const int g = lane >> 3;
    const uint32_t b_row = (g >> 1) * 8 + (lane & 7);
    const uint32_t b_k8  = (g & 1) * 8;

    #pragma unroll
    for (int ks = 0; ks < 2; ++ks) {
        uint32_t aq[4], bk[4][4];
        uint32_t akoff = (ks * 16 + a_k8) * 2;
        uint32_t bkoff = (ks * 16 + b_k8) * 2;
        ldsm4(aq, sQ + a_row * AROWB + akoff);
        #pragma unroll
        for (int nt = 0; nt < 4; ++nt)
            ldsm4(bk[nt], sK + (b_row + nt * 16) * AROWB + bkoff);
        #pragma unroll
        for (int nt = 0; nt < 8; ++nt) {
            int q = nt >> 1, hh = (nt & 1) * 2;
            MMA_F16(s[nt], aq[0], aq[1], aq[2], aq[3], bk[q][hh], bk[q][hh + 1]);
        }
    }

    // ---- bias + mask ----
    const int r = wid * 16 + (lane >> 2);
    const int cbase = (lane & 3) * 2;
    const float* brow = bias + ((size_t)h << 12);
    const float* mrow = mask + ((size_t)(bw & (NW_ - 1)) << 12);
    #pragma unroll
    for (int nt = 0; nt < 8; ++nt) {
        int c = nt * 8 + cbase;
        float2 b0 = *(const float2*)(brow + r * 64 + c);
        float2 m0 = *(const float2*)(mrow + r * 64 + c);
        float2 b1 = *(const float2*)(brow + (r + 8) * 64 + c);
        float2 m1 = *(const float2*)(mrow + (r + 8) * 64 + c);
        s[nt][0] += b0.x + m0.x; s[nt][1] += b0.y + m0.y;
        s[nt][2] += b1.x + m1.x; s[nt][3] += b1.y + m1.y;
    }

    // ---- softmax over 64 cols (4 lanes per row) ----
    {
        float mx0 = -1e30f, mx1 = -1e30f;
        #pragma unroll
        for (int nt = 0; nt < 8; ++nt) {
            mx0 = fmaxf(mx0, fmaxf(s[nt][0], s[nt][1]));
            mx1 = fmaxf(mx1, fmaxf(s[nt][2], s[nt][3]));
        }
        #pragma unroll
        for (int o = 1; o <= 2; o <<= 1) {
            mx0 = fmaxf(mx0, __shfl_xor_sync(0xffffffffu, mx0, o));
            mx1 = fmaxf(mx1, __shfl_xor_sync(0xffffffffu, mx1, o));
        }
        float sm0 = 0.f, sm1 = 0.f;
        #pragma unroll
        for (int nt = 0; nt < 8; ++nt) {
            s[nt][0] = __expf(s[nt][0] - mx0); sm0 += s[nt][0];
            s[nt][1] = __expf(s[nt][1] - mx0); sm0 += s[nt][1];
            s[nt][2] = __expf(s[nt][2] - mx1); sm1 += s[nt][2];
            s[nt][3] = __expf(s[nt][3] - mx1); sm1 += s[nt][3];
        }
        #pragma unroll
        for (int o = 1; o <= 2; o <<= 1) {
            sm0 += __shfl_xor_sync(0xffffffffu, sm0, o);
            sm1 += __shfl_xor_sync(0xffffffffu, sm1, o);
        }
        float i0 = 1.f / sm0, i1 = 1.f / sm1;
        #pragma unroll
        for (int nt = 0; nt < 8; ++nt) {
            s[nt][0] *= i0; s[nt][1] *= i0;
            s[nt][2] *= i1; s[nt][3] *= i1;
        }
    }

    // ---- Phase 2: O = P @ V ----
    float o[4][4];
    #pragma unroll
    for (int nt = 0; nt < 4; ++nt)
        #pragma unroll
        for (int c = 0; c < 4; ++c) o[nt][c] = 0.f;

    const uint32_t v_row = lane & 15;
    const uint32_t v_c16 = (lane >> 4) * 16;
    #pragma unroll
    for (int kt = 0; kt < 4; ++kt) {
        __half2 pa0 = __floats2half2_rn(s[2 * kt][0], s[2 * kt][1]);
        __half2 pa1 = __floats2half2_rn(s[2 * kt][2], s[2 * kt][3]);
        __half2 pa2 = __floats2half2_rn(s[2 * kt + 1][0], s[2 * kt + 1][1]);
        __half2 pa3 = __floats2half2_rn(s[2 * kt + 1][2], s[2 * kt + 1][3]);
        uint32_t a0 = *(uint32_t*)&pa0, a1 = *(uint32_t*)&pa1;
        uint32_t a2 = *(uint32_t*)&pa2, a3 = *(uint32_t*)&pa3;
        uint32_t vb0[4], vb1[4];
        ldsm4t(vb0, sV + (kt * 16 + v_row) * AROWB + v_c16);
        ldsm4t(vb1, sV + (kt * 16 + v_row) * AROWB + 32 + v_c16);
        MMA_F16(o[0], a0, a1, a2, a3, vb0[0], vb0[1]);
        MMA_F16(o[1], a0, a1, a2, a3, vb0[2], vb0[3]);
        MMA_F16(o[2], a0, a1, a2, a3, vb1[0], vb1[1]);
        MMA_F16(o[3], a0, a1, a2, a3, vb1[2], vb1[3]);
    }

    // ---- write O (fp16) ----
    __half* obase = outh + (size_t)bw * NTOK * DIM_ + (size_t)h * HD_;
    #pragma unroll
    for (int nt = 0; nt < 4; ++nt) {
        int c = nt * 8 + cbase;
        __half2 h0 = __floats2half2_rn(o[nt][0], o[nt][1]);
        __half2 h1 = __floats2half2_rn(o[nt][2], o[nt][3]);
        *(__half2*)(obase + (size_t)r * DIM_ + c) = h0;
        *(__half2*)(obase + (size_t)(r + 8) * DIM_ + c) = h1;
    }
}

// ---------------------------------------------------------------------------
extern "C" void kernel_launch(void* const* d_in, const int* in_sizes, int n_in,
                              void* d_out, int out_size)
{
    const float* x       = (const float*)d_in[0];
    const float* mask    = (const float*)d_in[1];
    const float* qkv_w   = (const float*)d_in[2];
    const float* qkv_b   = (const float*)d_in[3];
    const float* table   = (const float*)d_in[4];
    const float* proj_w  = (const float*)d_in[5];
    const float* proj_b  = (const float*)d_in[6];
    const int*   rel_idx = (const int*)d_in[7];
    float* out = (float*)d_out;

    __half *qkvh, *xh, *ah, *w1h, *w2h;
    float *b1, *bias;
    cudaGetSymbolAddress((void**)&qkvh, g_qkvh);
    cudaGetSymbolAddress((void**)&xh, g_xh);
    cudaGetSymbolAddress((void**)&ah, g_ah);
    cudaGetSymbolAddress((void**)&w1h, g_w1h);
    cudaGetSymbolAddress((void**)&w2h, g_w2h);
    cudaGetSymbolAddress((void**)&b1, g_b1);
    cudaGetSymbolAddress((void**)&bias, g_bias);

    const int gemm_smem = NSTAGE * STAGE_B;   // 61440
    cudaFuncSetAttribute(gemm_h<__half>, cudaFuncAttributeMaxDynamicSharedMemorySize,
                         gemm_smem);
    cudaFuncSetAttribute(gemm_h<float>, cudaFuncAttributeMaxDynamicSharedMemorySize,
                         gemm_smem);

    // 1) prep
    {
        int n1 = MTOT * DIM_;
        convert_half<<<n1 / 4 / 256, 256>>>(x, xh, n1);
        convert_w1<<<TRIPLE * DIM_ / 4 / 256, 256>>>(qkv_w, w1h);
        int n3 = DIM_ * DIM_;
        convert_half<<<n3 / 4 / 256, 256>>>(proj_w, w2h, n3);
        prep_misc<<<64, 256>>>(qkv_b, b1, table, rel_idx, bias);
    }
    // 2) QKV GEMM -> fp16 qkv
    {
        dim3 grid(TRIPLE / 128, MTOT / 128);
        gemm_h<__half><<<grid, 256, gemm_smem>>>(xh, w1h, b1, qkvh, TRIPLE, DIM_);
    }
    // 3) attention (tensor-core)
    {
        dim3 grid(NH_, BW_);
        attn_mma<<<grid, 128>>>(qkvh, mask, bias, ah);
    }
    // 4) proj GEMM -> fp32 out
    {
        dim3 grid(DIM_ / 128, MTOT / 128);
        gemm_h<float><<<grid, 256, gemm_smem>>>(ah, w2h, proj_b, out, DIM_, DIM_);
    }
}

// round 11
// speedup vs baseline: 1.7492x; 1.1675x over previous
#include <cuda_runtime.h>
#include <cuda_fp16.h>
#include <cstdint>

// Problem constants
#define BW_    1024
#define NTOK   64
#define DIM_   512
#define NH_    16
#define HD_    32
#define NW_    64
#define TRIPLE 1536
#define MTOT   (BW_ * NTOK)            /* 65536 */
#define SCALE_ 0.17677669529663687f
#define HCOLS  96                      /* q|k|v cols per head */

// ---------------------------------------------------------------------------
// Scratch (allocation-free rule: __device__ globals)
// ---------------------------------------------------------------------------
__device__ __half g_xh[(size_t)MTOT * DIM_];
__device__ __half g_ah[(size_t)MTOT * DIM_];
__device__ __half g_w1p[TRIPLE * DIM_];              // head-permuted qkv weight
__device__ __half g_w2h[DIM_ * DIM_];
__device__ float  g_b1p[TRIPLE];                      // permuted, prescaled bias
__device__ float  g_bias[NH_ * NTOK * NTOK];          // gathered rel bias

// ---------------------------------------------------------------------------
// helpers
// ---------------------------------------------------------------------------
__device__ __forceinline__ uint32_t smem_u32(const void* p) {
    uint32_t a;
    asm("{ .reg .u64 t; cvta.to.shared.u64 t, %1; cvt.u32.u64 %0, t; }"
        : "=r"(a) : "l"(p));
    return a;
}

#define CP_ASYNC16(smem_addr, gptr) \
    asm volatile("cp.async.cg.shared.global [%0], [%1], 16;" \
                 :: "r"((uint32_t)(smem_addr)), "l"(gptr) : "memory")
#define CP_ASYNC_COMMIT() asm volatile("cp.async.commit_group;" ::: "memory")
#define CP_ASYNC_WAIT0()  asm volatile("cp.async.wait_group 0;" ::: "memory")
#define CP_ASYNC_WAIT1()  asm volatile("cp.async.wait_group 1;" ::: "memory")

__device__ __forceinline__ void ldsm4(uint32_t* r, uint32_t addr) {
    asm volatile("ldmatrix.sync.aligned.m8n8.x4.shared.b16 {%0,%1,%2,%3}, [%4];"
                 : "=r"(r[0]), "=r"(r[1]), "=r"(r[2]), "=r"(r[3]) : "r"(addr));
}
__device__ __forceinline__ void ldsm4t(uint32_t* r, uint32_t addr) {
    asm volatile("ldmatrix.sync.aligned.m8n8.x4.trans.shared.b16 {%0,%1,%2,%3}, [%4];"
                 : "=r"(r[0]), "=r"(r[1]), "=r"(r[2]), "=r"(r[3]) : "r"(addr));
}

#define MMA_F16(d, a0, a1, a2, a3, b0, b1) \
    asm volatile("mma.sync.aligned.m16n8k16.row.col.f32.f16.f16.f32 " \
        "{%0,%1,%2,%3}, {%4,%5,%6,%7}, {%8,%9}, {%0,%1,%2,%3};" \
        : "+f"((d)[0]), "+f"((d)[1]), "+f"((d)[2]), "+f"((d)[3]) \
        : "r"(a0), "r"(a1), "r"(a2), "r"(a3), "r"(b0), "r"(b1))

// ---------------------------------------------------------------------------
// Prep kernels
// ---------------------------------------------------------------------------
__global__ __launch_bounds__(256) void convert_half(
    const float* __restrict__ in, __half* __restrict__ out, int n)
{
    int i = (blockIdx.x * 256 + threadIdx.x) * 4;
    if (i >= n) return;
    float4 v = *(const float4*)(in + i);
    __half h[4] = {__float2half(v.x), __float2half(v.y),
                   __float2half(v.z), __float2half(v.w)};
    *(uint2*)(out + i) = *(uint2*)h;
}

// Head-permuted qkv weight: out row p = h*96 + s*32 + d  <-  in row s*512 + h*32 + d.
// q section (s==0) prescaled by SCALE_.
__global__ __launch_bounds__(256) void prep_w1p(
    const float* __restrict__ in, __half* __restrict__ out)
{
    int i = (blockIdx.x * 256 + threadIdx.x) * 4;   // over 1536*512
    int p = i >> 9;              // out row
    int k = i & 511;
    int h = p / HCOLS;
    int rem = p - h * HCOLS;
    int s = rem >> 5, d = rem & 31;
    float sc = (s == 0) ? SCALE_ : 1.0f;
    const float* src = in + ((size_t)(s * 512 + h * 32 + d) << 9) + k;
    float4 v = *(const float4*)src;
    __half hh[4] = {__float2half(v.x * sc), __float2half(v.y * sc),
                    __float2half(v.z * sc), __float2half(v.w * sc)};
    *(uint2*)(out + (size_t)p * 512 + k) = *(uint2*)hh;
}

__global__ __launch_bounds__(256) void prep_misc(
    const float* __restrict__ qkv_b, float* __restrict__ b1p,
    const float* __restrict__ table, const int* __restrict__ rel_index,
    float* __restrict__ bias)
{
    int idx = blockIdx.x * 256 + threadIdx.x;
    if (idx < TRIPLE) {
        int h = idx / HCOLS;
        int rem = idx - h * HCOLS;
        int s = rem >> 5, d = rem & 31;
        b1p[idx] = qkv_b[s * 512 + h * 32 + d] * (s == 0 ? SCALE_ : 1.0f);
    }
    for (int t = idx; t < NH_ * NTOK * NTOK; t += gridDim.x * 256) {
        int h = t >> 12, ij = t & 4095;
        bias[t] = table[rel_index[ij] * NH_ + h];
    }
}

// ---------------------------------------------------------------------------
// Fused QKV-GEMM + window attention.
// grid (NH_, 512). CTA: M=128 rows (2 windows) x N=96 cols (one head's q|k|v).
// Mainloop: 3-stage cp.async, warp tile 32x48 (8 warps: 4 my x 2 nx).
// Epilogue: qkv+bias -> padded smem; 4 warps per window run mma attention.
// ---------------------------------------------------------------------------
#define ROWB 80
#define A_TILE_B (128 * ROWB)               /* 10240 */
#define B_TILE_B (HCOLS * ROWB)             /* 7680  */
#define STAGE_B  (A_TILE_B + B_TILE_B)      /* 17920 */
#define NSTAGE 3
#define FUSED_SMEM (NSTAGE * STAGE_B)       /* 53760 */
#define AROWB 80
#define WIN_B (3 * 64 * AROWB)              /* 15360 per window */

__global__ __launch_bounds__(256, 2)
void gemm1_attn(const __half* __restrict__ A,      // x fp16 (65536,512)
                const __half* __restrict__ W,      // permuted w1 (1536,512)
                const float* __restrict__ b1p,     // permuted bias
                const float* __restrict__ mask,    // (NW,64,64)
                const float* __restrict__ bias,    // (NH,64,64)
                __half* __restrict__ outh)         // ah (65536,512)
{
    extern __shared__ char smem[];
    const uint32_t sbase = smem_u32(smem);

    const int tid  = threadIdx.x;
    const int lane = tid & 31;
    const int wid  = tid >> 5;
    const int wy   = wid & 3;          // row group (32 rows)
    const int wx   = wid >> 2;         // col group (48 cols)
    const int h    = blockIdx.x;
    const int m0   = blockIdx.y * 128;

    float acc[2][6][4];
    #pragma unroll
    for (int a = 0; a < 2; ++a)
        #pragma unroll
        for (int b = 0; b < 6; ++b)
            #pragma unroll
            for (int c = 0; c < 4; ++c) acc[a][b][c] = 0.f;

    const int nIter = DIM_ / 32;   // 16

    auto load_stage = [&](int s, int k0) {
        uint32_t st = sbase + s * STAGE_B;
        // A: 128 rows x 4 chunks = 512 float4
        #pragma unroll
        for (int j = 0; j < 2; ++j) {
            int lin = tid + j * 256;
            int r = lin >> 2, c = lin & 3;
            CP_ASYNC16(st + r * ROWB + c * 16,
                       A + (size_t)(m0 + r) * DIM_ + k0 + c * 8);
        }
        // B: 96 rows x 4 chunks = 384 float4
        {
            int r = tid >> 2, c = tid & 3;
            CP_ASYNC16(st + A_TILE_B + r * ROWB + c * 16,
                       W + (size_t)(h * HCOLS + r) * DIM_ + k0 + c * 8);
            if (tid < 128) {
                int lin = 256 + tid;
                int r2 = lin >> 2, c2 = lin & 3;
                CP_ASYNC16(st + A_TILE_B + r2 * ROWB + c2 * 16,
                           W + (size_t)(h * HCOLS + r2) * DIM_ + k0 + c2 * 8);
            }
        }
        CP_ASYNC_COMMIT();
    };

    load_stage(0, 0);
    load_stage(1, 32);

    const uint32_t a_row = wy * 32 + (lane & 15);
    const uint32_t a_k8  = (lane >> 4) * 8;
    const int g = lane >> 3;
    const uint32_t b_rowb = wx * 48 + (g >> 1) * 8 + (lane & 7);
    const uint32_t b_k8  = (g & 1) * 8;

    for (int it = 0; it < nIter; ++it) {
        if (it + 1 < nIter) { CP_ASYNC_WAIT1(); } else { CP_ASYNC_WAIT0(); }
        __syncthreads();
        if (it + 2 < nIter) load_stage((it + 2) % NSTAGE, (it + 2) * 32);

        uint32_t st = sbase + (it % NSTAGE) * STAGE_B;
        uint32_t sA = st, sB = st + A_TILE_B;

        #pragma unroll
        for (int ks = 0; ks < 2; ++ks) {
            uint32_t ah[2][4], bh[3][4];
            uint32_t akoff = (ks * 16 + a_k8) * 2;
            uint32_t bkoff = (ks * 16 + b_k8) * 2;
            #pragma unroll
            for (int mt = 0; mt < 2; ++mt)
                ldsm4(ah[mt], sA + (a_row + mt * 16) * ROWB + akoff);
            #pragma unroll
            for (int nt = 0; nt < 3; ++nt)
                ldsm4(bh[nt], sB + (b_rowb + nt * 16) * ROWB + bkoff);
            #pragma unroll
            for (int mt = 0; mt < 2; ++mt)
                #pragma unroll
                for (int nt = 0; nt < 6; ++nt) {
                    int q = nt >> 1, hh = (nt & 1) * 2;
                    MMA_F16(acc[mt][nt], ah[mt][0], ah[mt][1], ah[mt][2],
                            ah[mt][3], bh[q][hh], bh[q][hh + 1]);
                }
        }
    }
    __syncthreads();   // all warps done with stage smem before qkv reuse

    // ---- Epilogue: deposit q,k,v (+bias) into per-window padded smem ----
    const int cbase = (lane & 3) * 2;
    #pragma unroll
    for (int mt = 0; mt < 2; ++mt) {
        int wr = wy * 32 + mt * 16 + (lane >> 2);   // 0..127
        int win = wr >> 6;
        int riw = wr & 63;
        uint32_t wb = sbase + win * WIN_B;
        #pragma unroll
        for (int nt = 0; nt < 6; ++nt) {
            int col = wx * 48 + (nt >> 1) * 16 + (nt & 1) * 8 + cbase;
            float b0 = __ldg(b1p + h * HCOLS + col);
            float b1v = __ldg(b1p + h * HCOLS + col + 1);
            __half2 h0 = __floats2half2_rn(acc[mt][nt][0] + b0, acc[mt][nt][1] + b1v);
            __half2 h1 = __floats2half2_rn(acc[mt][nt][2] + b0, acc[mt][nt][3] + b1v);
            int sect = col >> 5;           // 0=q 1=k 2=v
            int d = col & 31;
            uint32_t base = wb + sect * (64 * AROWB) + d * 2;
            *(__half2*)(smem + (base - sbase) + riw * AROWB) = h0;
            *(__half2*)(smem + (base - sbase) + (riw + 8) * AROWB) = h1;
        }
    }
    __syncthreads();

    // ---- Attention: 4 warps per window ----
    const int lw  = wid & 3;           // local warp in window
    const int win = wid >> 2;
    const int bw  = blockIdx.y * 2 + win;
    const uint32_t sQ = sbase + win * WIN_B;
    const uint32_t sK = sQ + 64 * AROWB;
    const uint32_t sV = sQ + 2 * 64 * AROWB;

    float s[8][4];
    #pragma unroll
    for (int nt = 0; nt < 8; ++nt)
        #pragma unroll
        for (int c = 0; c < 4; ++c) s[nt][c] = 0.f;

    const uint32_t q_row = lw * 16 + (lane & 15);
    const uint32_t q_k8  = (lane >> 4) * 8;
    const uint32_t k_row = (g >> 1) * 8 + (lane & 7);
    const uint32_t k_k8  = (g & 1) * 8;

    #pragma unroll
    for (int ks = 0; ks < 2; ++ks) {
        uint32_t aq[4], bk[4][4];
        uint32_t akoff = (ks * 16 + q_k8) * 2;
        uint32_t bkoff = (ks * 16 + k_k8) * 2;
        ldsm4(aq, sQ + q_row * AROWB + akoff);
        #pragma unroll
        for (int nt = 0; nt < 4; ++nt)
            ldsm4(bk[nt], sK + (k_row + nt * 16) * AROWB + bkoff);
        #pragma unroll
        for (int nt = 0; nt < 8; ++nt) {
            int q = nt >> 1, hh = (nt & 1) * 2;
            MMA_F16(s[nt], aq[0], aq[1], aq[2], aq[3], bk[q][hh], bk[q][hh + 1]);
        }
    }

    // bias + mask
    const int r = lw * 16 + (lane >> 2);
    const float* brow = bias + ((size_t)h << 12);
    const float* mrow = mask + ((size_t)(bw & (NW_ - 1)) << 12);
    #pragma unroll
    for (int nt = 0; nt < 8; ++nt) {
        int c = nt * 8 + cbase;
        float2 b0 = *(const float2*)(brow + r * 64 + c);
        float2 m0 = *(const float2*)(mrow + r * 64 + c);
        float2 b1 = *(const float2*)(brow + (r + 8) * 64 + c);
        float2 m1 = *(const float2*)(mrow + (r + 8) * 64 + c);
        s[nt][0] += b0.x + m0.x; s[nt][1] += b0.y + m0.y;
        s[nt][2] += b1.x + m1.x; s[nt][3] += b1.y + m1.y;
    }

    // softmax (4 lanes per row)
    {
        float mx0 = -1e30f, mx1 = -1e30f;
        #pragma unroll
        for (int nt = 0; nt < 8; ++nt) {
            mx0 = fmaxf(mx0, fmaxf(s[nt][0], s[nt][1]));
            mx1 = fmaxf(mx1, fmaxf(s[nt][2], s[nt][3]));
        }
        #pragma unroll
        for (int o = 1; o <= 2; o <<= 1) {
            mx0 = fmaxf(mx0, __shfl_xor_sync(0xffffffffu, mx0, o));
            mx1 = fmaxf(mx1, __shfl_xor_sync(0xffffffffu, mx1, o));
        }
        float sm0 = 0.f, sm1 = 0.f;
        #pragma unroll
        for (int nt = 0; nt < 8; ++nt) {
            s[nt][0] = __expf(s[nt][0] - mx0); sm0 += s[nt][0];
            s[nt][1] = __expf(s[nt][1] - mx0); sm0 += s[nt][1];
            s[nt][2] = __expf(s[nt][2] - mx1); sm1 += s[nt][2];
            s[nt][3] = __expf(s[nt][3] - mx1); sm1 += s[nt][3];
        }
        #pragma unroll
        for (int o = 1; o <= 2; o <<= 1) {
            sm0 += __shfl_xor_sync(0xffffffffu, sm0, o);
            sm1 += __shfl_xor_sync(0xffffffffu, sm1, o);
        }
        float i0 = 1.f / sm0, i1 = 1.f / sm1;
        #pragma unroll
        for (int nt = 0; nt < 8; ++nt) {
            s[nt][0] *= i0; s[nt][1] *= i0;
            s[nt][2] *= i1; s[nt][3] *= i1;
        }
    }

    // O = P @ V
    float o[4][4];
    #pragma unroll
    for (int nt = 0; nt < 4; ++nt)
        #pragma unroll
        for (int c = 0; c < 4; ++c) o[nt][c] = 0.f;

    const uint32_t v_row = lane & 15;
    const uint32_t v_c16 = (lane >> 4) * 16;
    #pragma unroll
    for (int kt = 0; kt < 4; ++kt) {
        __half2 pa0 = __floats2half2_rn(s[2 * kt][0], s[2 * kt][1]);
        __half2 pa1 = __floats2half2_rn(s[2 * kt][2], s[2 * kt][3]);
        __half2 pa2 = __floats2half2_rn(s[2 * kt + 1][0], s[2 * kt + 1][1]);
        __half2 pa3 = __floats2half2_rn(s[2 * kt + 1][2], s[2 * kt + 1][3]);
        uint32_t a0 = *(uint32_t*)&pa0, a1 = *(uint32_t*)&pa1;
        uint32_t a2 = *(uint32_t*)&pa2, a3 = *(uint32_t*)&pa3;
        uint32_t vb0[4], vb1[4];
        ldsm4t(vb0, sV + (kt * 16 + v_row) * AROWB + v_c16);
        ldsm4t(vb1, sV + (kt * 16 + v_row) * AROWB + 32 + v_c16);
        MMA_F16(o[0], a0, a1, a2, a3, vb0[0], vb0[1]);
        MMA_F16(o[1], a0, a1, a2, a3, vb0[2], vb0[3]);
        MMA_F16(o[2], a0, a1, a2, a3, vb1[0], vb1[1]);
        MMA_F16(o[3], a0, a1, a2, a3, vb1[2], vb1[3]);
    }

    __half* obase = outh + (size_t)bw * NTOK * DIM_ + (size_t)h * HD_;
    #pragma unroll
    for (int nt = 0; nt < 4; ++nt) {
        int c = nt * 8 + cbase;
        __half2 h0 = __floats2half2_rn(o[nt][0], o[nt][1]);
        __half2 h1 = __floats2half2_rn(o[nt][2], o[nt][3]);
        *(__half2*)(obase + (size_t)r * DIM_ + c) = h0;
        *(__half2*)(obase + (size_t)(r + 8) * DIM_ + c) = h1;
    }
}

// ---------------------------------------------------------------------------
// fp16 GEMM (NT) for the output projection (fp32 out). Proven R5 config.
// ---------------------------------------------------------------------------
#define GTILE_B (128 * ROWB)
#define GSTAGE_B (2 * GTILE_B)
#define GNSTAGE 3

__global__ __launch_bounds__(256, 2)
void gemm_proj(const __half* __restrict__ A, const __half* __restrict__ B,
               const float* __restrict__ bias, float* __restrict__ C,
               int Nn, int K)
{
    extern __shared__ char smem[];
    const uint32_t sbase = smem_u32(smem);

    const int tid  = threadIdx.x;
    const int lane = tid & 31;
    const int wid  = tid >> 5;
    const int wm   = (wid & 3) * 32;
    const int wn   = (wid >> 2) * 64;
    const int m0 = blockIdx.y * 128;
    const int n0 = blockIdx.x * 128;

    float acc[2][8][4];
    #pragma unroll
    for (int a = 0; a < 2; ++a)
        #pragma unroll
        for (int b = 0; b < 8; ++b)
            #pragma unroll
            for (int c = 0; c < 4; ++c) acc[a][b][c] = 0.f;

    const int nIter = K / 32;

    auto load_stage = [&](int s, int k0) {
        uint32_t st = sbase + s * GSTAGE_B;
        #pragma unroll
        for (int j = 0; j < 2; ++j) {
            int lin = tid + j * 256;
            int r = lin >> 2, c = lin & 3;
            uint32_t dst = r * ROWB + c * 16;
            CP_ASYNC16(st + dst, A + (size_t)(m0 + r) * K + k0 + c * 8);
            CP_ASYNC16(st + GTILE_B + dst, B + (size_t)(n0 + r) * K + k0 + c * 8);
        }
        CP_ASYNC_COMMIT();
    };

    load_stage(0, 0);
    load_stage(1, 32);

    const uint32_t a_row = wm + (lane & 15);
    const uint32_t a_k8  = (lane >> 4) * 8;
    const int g = lane >> 3;
    const uint32_t b_row = wn + (g >> 1) * 8 + (lane & 7);
    const uint32_t b_k8  = (g & 1) * 8;

    for (int it = 0; it < nIter; ++it) {
        if (it + 1 < nIter) { CP_ASYNC_WAIT1(); } else { CP_ASYNC_WAIT0(); }
        __syncthreads();
        if (it + 2 < nIter) load_stage((it + 2) % GNSTAGE, (it + 2) * 32);

        uint32_t st = sbase + (it % GNSTAGE) * GSTAGE_B;
        uint32_t sA = st, sB = st + GTILE_B;

        #pragma unroll
        for (int ks = 0; ks < 2; ++ks) {
            uint32_t ah[2][4], bh[4][4];
            uint32_t akoff = (ks * 16 + a_k8) * 2;
            uint32_t bkoff = (ks * 16 + b_k8) * 2;
            #pragma unroll
            for (int mt = 0; mt < 2; ++mt)
                ldsm4(ah[mt], sA + (a_row + mt * 16) * ROWB + akoff);
            #pragma unroll
            for (int nt = 0; nt < 4; ++nt)
                ldsm4(bh[nt], sB + (b_row + nt * 16) * ROWB + bkoff);
            #pragma unroll
            for (int mt = 0; mt < 2; ++mt)
                #pragma unroll
                for (int nt = 0; nt < 8; ++nt) {
                    int q = nt >> 1, h = (nt & 1) * 2;
                    MMA_F16(acc[mt][nt], ah[mt][0], ah[mt][1], ah[mt][2],
                            ah[mt][3], bh[q][h], bh[q][h + 1]);
                }
        }
    }

    #pragma unroll
    for (int mt = 0; mt < 2; ++mt) {
        int r0 = m0 + wm + mt * 16 + (lane >> 2);
        #pragma unroll
        for (int nt = 0; nt < 8; ++nt) {
            int col = n0 + wn + (nt >> 1) * 16 + (nt & 1) * 8 + (lane & 3) * 2;
            float b0 = __ldg(bias + col), b1 = __ldg(bias + col + 1);
            float2 f0 = {acc[mt][nt][0] + b0, acc[mt][nt][1] + b1};
            float2 f1 = {acc[mt][nt][2] + b0, acc[mt][nt][3] + b1};
            *(float2*)(C + (size_t)r0 * Nn + col) = f0;
            *(float2*)(C + (size_t)(r0 + 8) * Nn + col) = f1;
        }
    }
}

// ---------------------------------------------------------------------------
extern "C" void kernel_launch(void* const* d_in, const int* in_sizes, int n_in,
                              void* d_out, int out_size)
{
    const float* x       = (const float*)d_in[0];
    const float* mask    = (const float*)d_in[1];
    const float* qkv_w   = (const float*)d_in[2];
    const float* qkv_b   = (const float*)d_in[3];
    const float* table   = (const float*)d_in[4];
    const float* proj_w  = (const float*)d_in[5];
    const float* proj_b  = (const float*)d_in[6];
    const int*   rel_idx = (const int*)d_in[7];
    float* out = (float*)d_out;

    __half *xh, *ah, *w1p, *w2h;
    float *b1p, *bias;
    cudaGetSymbolAddress((void**)&xh, g_xh);
    cudaGetSymbolAddress((void**)&ah, g_ah);
    cudaGetSymbolAddress((void**)&w1p, g_w1p);
    cudaGetSymbolAddress((void**)&w2h, g_w2h);
    cudaGetSymbolAddress((void**)&b1p, g_b1p);
    cudaGetSymbolAddress((void**)&bias, g_bias);

    cudaFuncSetAttribute(gemm1_attn, cudaFuncAttributeMaxDynamicSharedMemorySize,
                         FUSED_SMEM);
    const int proj_smem = GNSTAGE * GSTAGE_B;   // 61440
    cudaFuncSetAttribute(gemm_proj, cudaFuncAttributeMaxDynamicSharedMemorySize,
                         proj_smem);

    // 1) prep
    {
        int n1 = MTOT * DIM_;
        convert_half<<<n1 / 4 / 256, 256>>>(x, xh, n1);
        prep_w1p<<<TRIPLE * DIM_ / 4 / 256, 256>>>(qkv_w, w1p);
        int n3 = DIM_ * DIM_;
        convert_half<<<n3 / 4 / 256, 256>>>(proj_w, w2h, n3);
        prep_misc<<<64, 256>>>(qkv_b, b1p, table, rel_idx, bias);
    }
    // 2) fused QKV GEMM + attention -> fp16 ah
    {
        dim3 grid(NH_, MTOT / 128);
        gemm1_attn<<<grid, 256, FUSED_SMEM>>>(xh, w1p, b1p, mask, bias, ah);
    }
    // 3) proj GEMM -> fp32 out
    {
        dim3 grid(DIM_ / 128, MTOT / 128);
        gemm_proj<<<grid, 256, proj_smem>>>(ah, w2h, proj_b, out, DIM_, DIM_);
    }
}